// round 14
// baseline (speedup 1.0000x reference)
#include <cuda_runtime.h>
#include <cuda_fp16.h>
#include <math.h>
#include <stdint.h>

// ---------------------------------------------------------------------------
// Problem constants
// ---------------------------------------------------------------------------
#define TT   256
#define PP   256
#define EE   300
#define HH   256
#define NPOS 65536            // T*P
#define G4   1024             // 4H
#define D2H  512              // 2H
#define MM   50000
#define CC   16384
#define EP   320              // E padded to multiple of 32
#define MTILES ((MM + 127) / 128)   // 391

// ---------------------------------------------------------------------------
// Device scratch (static allocations only)
// ---------------------------------------------------------------------------
__device__ __half   g_GxF[(size_t)NPOS * G4];          // 134 MB fp16 (cols j*4+g)
__device__ __half   g_GxB[(size_t)NPOS * G4];          // 134 MB
__device__ unsigned g_pairKeys[(size_t)3 * CC * D2H];  // 100 MB
__device__ unsigned g_triKeys[(size_t)CC * D2H];       // 33 MB
__device__ float    g_pv[(size_t)3 * CC * D2H];        // 100 MB
__device__ float    g_tv[(size_t)CC * D2H];            // 33 MB
__device__ float    g_final[(size_t)CC * D2H];         // 33 MB
__device__ float    g_pbF[G4];                         // permuted biases
__device__ float    g_pbB[G4];
__device__ unsigned g_barCnt[16];                      // per (dir,ptile) barrier
__device__ unsigned g_barGen[16];

// fp16 operand buffers
__device__ __half g_xHi[(size_t)NPOS * EP];            // 42 MB (hi only)
__device__ __half g_wHiF[(size_t)G4 * EP];             // packed rows j*4+g
__device__ __half g_wHiB[(size_t)G4 * EP];
__device__ __half g_whhHiF[(size_t)G4 * HH];           // packed rows j*4+g
__device__ __half g_whhLoF[(size_t)G4 * HH];
__device__ __half g_whhHiB[(size_t)G4 * HH];
__device__ __half g_whhLoB[(size_t)G4 * HH];
__device__ __half g_flatHi[(size_t)NPOS * D2H];        // 67 MB
__device__ __half g_flatLo[(size_t)NPOS * D2H];        // used by LSTM only
__device__ __half g_pwHi[(size_t)3 * D2H * G4];        // pairWT [3][512][1024]
__device__ __half g_twHi[(size_t)D2H * 1536];          // triWT [512][1536]
__device__ __half g_aWHi[(size_t)D2H * 2048];
__device__ __half g_ftHi[(size_t)CC * 2048];           // 67 MB (hi only)

// ---------------------------------------------------------------------------
// Helpers
// ---------------------------------------------------------------------------
__device__ __forceinline__ uint32_t smem_u32(const void* p) {
    uint32_t a;
    asm("{ .reg .u64 t; cvta.to.shared.u64 t, %1; cvt.u32.u64 %0, t; }"
        : "=r"(a) : "l"(p));
    return a;
}

#define LDSM_X4(r, addr) \
    asm volatile("ldmatrix.sync.aligned.m8n8.x4.shared.b16 {%0,%1,%2,%3}, [%4];" \
        : "=r"((r)[0]), "=r"((r)[1]), "=r"((r)[2]), "=r"((r)[3]) : "r"(addr))

#define MMA_FP16(d, a, b) \
    asm volatile("mma.sync.aligned.m16n8k16.row.col.f32.f16.f16.f32 " \
        "{%0,%1,%2,%3}, {%4,%5,%6,%7}, {%8,%9}, {%0,%1,%2,%3};" \
        : "+f"((d)[0]), "+f"((d)[1]), "+f"((d)[2]), "+f"((d)[3]) \
        : "r"((a)[0]), "r"((a)[1]), "r"((a)[2]), "r"((a)[3]), \
          "r"((b)[0]), "r"((b)[1]))

#define CP_ASYNC16(dst, src) \
    asm volatile("cp.async.cg.shared.global [%0], [%1], 16;" \
                 :: "r"(dst), "l"(src))
#define CP_COMMIT() asm volatile("cp.async.commit_group;" ::: "memory")
#define CP_WAIT(n)  asm volatile("cp.async.wait_group %0;" :: "n"(n) : "memory")

__device__ __forceinline__ float sigmoidf_(float x) { return 1.0f / (1.0f + expf(-x)); }

__device__ __forceinline__ unsigned fmap(float f) {
    unsigned b = __float_as_uint(f);
    return (b & 0x80000000u) ? ~b : (b | 0x80000000u);
}
__device__ __forceinline__ float funmap(unsigned u) {
    return (u & 0x80000000u) ? __uint_as_float(u & 0x7FFFFFFFu)
                             : __uint_as_float(~u);
}
__device__ __forceinline__ float warpReduceSum(float v) {
    #pragma unroll
    for (int o = 16; o > 0; o >>= 1) v += __shfl_down_sync(0xffffffffu, v, o);
    return v;
}
__device__ __forceinline__ float blockReduceSum256(float v) {
    __shared__ float sh[8];
    int lane = threadIdx.x & 31, wid = threadIdx.x >> 5;
    v = warpReduceSum(v);
    if (lane == 0) sh[wid] = v;
    __syncthreads();
    v = (threadIdx.x < 8) ? sh[threadIdx.x] : 0.0f;
    if (wid == 0) v = warpReduceSum(v);
    return v;
}
__device__ __forceinline__ void splith(float f, __half& h, __half& l) {
    h = __float2half(f);
    l = __float2half(f - __half2float(h));
}

// per-(dir,ptile) group barrier
__device__ __forceinline__ void group_barrier(int bidx, int tid, unsigned nCTA) {
    __syncthreads();
    if (tid == 0) {
        __threadfence();
        unsigned gen = atomicAdd(&g_barGen[bidx], 0u);
        unsigned prev = atomicAdd(&g_barCnt[bidx], 1u);
        if (prev == nCTA - 1u) {
            atomicExch(&g_barCnt[bidx], 0u);
            __threadfence();
            atomicAdd(&g_barGen[bidx], 1u);
        } else {
            while (atomicAdd(&g_barGen[bidx], 0u) == gen) { __nanosleep(32); }
        }
        __threadfence();
    }
    __syncthreads();
}

// ---------------------------------------------------------------------------
// Shared GEMM tile constants
// ---------------------------------------------------------------------------
#define RSZ   80
#define TILEB (128 * RSZ)       // 10240
#define STAGE2 (2 * TILEB)      // 20480 (Ahi, Bhi)
#define SMEM_G1 (2 * STAGE2)    // 40960

// ---------------------------------------------------------------------------
// fp16 1-term GEMM, fp32 output: C[M,N] = Ahi @ Bhi^T + bias
// CTA tile 128x128, 256 threads (8 warps: 2 M x 4 N; warp tile 64x32).
// ---------------------------------------------------------------------------
__global__ __launch_bounds__(256, 2)
void gemm_fp16x1_kernel(const __half* __restrict__ Ahi,
                        const __half* __restrict__ Bhi,
                        const float* __restrict__ bias,
                        float* __restrict__ C, int K) {
    extern __shared__ char smem[];
    const uint32_t sb = smem_u32(smem);
    const int tid = threadIdx.x, lane = tid & 31, wid = tid >> 5;
    const int m0 = blockIdx.y * 128, n0 = blockIdx.x * 128;
    const int ldc = gridDim.x * 128;
    const int wm = wid & 1, wn = wid >> 1;

    float acc[4][4][4];
    #pragma unroll
    for (int i = 0; i < 4; ++i)
        #pragma unroll
        for (int j = 0; j < 4; ++j)
            #pragma unroll
            for (int q = 0; q < 4; ++q) acc[i][j][q] = 0.0f;

    const int nch = K >> 5;
    const int r0c = (2 * tid) >> 2, ch0 = (2 * tid) & 3;
    const int r1c = (2 * tid + 1) >> 2, ch1 = (2 * tid + 1) & 3;
    const int rA = lane & 15;
    const int cA = lane >> 4;

    #define LOAD_STAGE(cc)                                                      \
    do {                                                                        \
        const int kb = (cc) << 5;                                               \
        const uint32_t dst = sb + ((cc) & 1) * STAGE2;                          \
        CP_ASYNC16(dst + 0 * TILEB + r0c * RSZ + ch0 * 16,                      \
                   Ahi + (size_t)(m0 + r0c) * K + kb + ch0 * 8);                \
        CP_ASYNC16(dst + 0 * TILEB + r1c * RSZ + ch1 * 16,                      \
                   Ahi + (size_t)(m0 + r1c) * K + kb + ch1 * 8);                \
        CP_ASYNC16(dst + 1 * TILEB + r0c * RSZ + ch0 * 16,                      \
                   Bhi + (size_t)(n0 + r0c) * K + kb + ch0 * 8);                \
        CP_ASYNC16(dst + 1 * TILEB + r1c * RSZ + ch1 * 16,                      \
                   Bhi + (size_t)(n0 + r1c) * K + kb + ch1 * 8);                \
        CP_COMMIT();                                                            \
    } while (0)

    LOAD_STAGE(0);

    for (int c = 0; c < nch; ++c) {
        if (c + 1 < nch) { LOAD_STAGE(c + 1); CP_WAIT(1); }
        else             { CP_WAIT(0); }
        __syncthreads();

        const uint32_t s = sb + (c & 1) * STAGE2;
        const uint32_t aHiB = s, bHiB = s + TILEB;

        #pragma unroll
        for (int ks = 0; ks < 2; ++ks) {
            const uint32_t colOff = (uint32_t)(ks * 2 + cA) * 16;
            uint32_t aHi[4][4], bHi[4][2];
            #pragma unroll
            for (int mt = 0; mt < 4; ++mt) {
                uint32_t ad = (uint32_t)(wm * 64 + mt * 16 + rA) * RSZ + colOff;
                LDSM_X4(aHi[mt], aHiB + ad);
            }
            #pragma unroll
            for (int nh = 0; nh < 2; ++nh) {
                uint32_t bd = (uint32_t)(wn * 32 + nh * 16 + rA) * RSZ + colOff;
                uint32_t t[4];
                LDSM_X4(t, bHiB + bd);
                bHi[nh * 2 + 0][0] = t[0]; bHi[nh * 2 + 0][1] = t[2];
                bHi[nh * 2 + 1][0] = t[1]; bHi[nh * 2 + 1][1] = t[3];
            }
            #pragma unroll
            for (int mt = 0; mt < 4; ++mt)
                #pragma unroll
                for (int nt = 0; nt < 4; ++nt)
                    MMA_FP16(acc[mt][nt], aHi[mt], bHi[nt]);
        }
        __syncthreads();
    }

    const int rr = lane >> 2, cc2 = (lane & 3) * 2;
    #pragma unroll
    for (int mt = 0; mt < 4; ++mt) {
        #pragma unroll
        for (int nt = 0; nt < 4; ++nt) {
            int row = m0 + wm * 64 + mt * 16 + rr;
            int col = n0 + wn * 32 + nt * 8 + cc2;
            float b0 = 0.f, b1 = 0.f;
            if (bias) { b0 = bias[col]; b1 = bias[col + 1]; }
            float2 v0 = make_float2(acc[mt][nt][0] + b0, acc[mt][nt][1] + b1);
            float2 v1 = make_float2(acc[mt][nt][2] + b0, acc[mt][nt][3] + b1);
            *(float2*)&C[(size_t)row * ldc + col] = v0;
            *(float2*)&C[(size_t)(row + 8) * ldc + col] = v1;
        }
    }
    #undef LOAD_STAGE
}

// ---------------------------------------------------------------------------
// fp16 1-term GEMM, fp16 output (for Gx): C[M,N] = Ahi @ Bhi^T + bias
// ---------------------------------------------------------------------------
__global__ __launch_bounds__(256, 2)
void gemm_fp16x1h_kernel(const __half* __restrict__ Ahi,
                         const __half* __restrict__ Bhi,
                         const float* __restrict__ bias,
                         __half* __restrict__ C, int K) {
    extern __shared__ char smem[];
    const uint32_t sb = smem_u32(smem);
    const int tid = threadIdx.x, lane = tid & 31, wid = tid >> 5;
    const int m0 = blockIdx.y * 128, n0 = blockIdx.x * 128;
    const int ldc = gridDim.x * 128;
    const int wm = wid & 1, wn = wid >> 1;

    float acc[4][4][4];
    #pragma unroll
    for (int i = 0; i < 4; ++i)
        #pragma unroll
        for (int j = 0; j < 4; ++j)
            #pragma unroll
            for (int q = 0; q < 4; ++q) acc[i][j][q] = 0.0f;

    const int nch = K >> 5;
    const int r0c = (2 * tid) >> 2, ch0 = (2 * tid) & 3;
    const int r1c = (2 * tid + 1) >> 2, ch1 = (2 * tid + 1) & 3;
    const int rA = lane & 15;
    const int cA = lane >> 4;

    #define LOAD_STAGE_H(cc)                                                    \
    do {                                                                        \
        const int kb = (cc) << 5;                                               \
        const uint32_t dst = sb + ((cc) & 1) * STAGE2;                          \
        CP_ASYNC16(dst + 0 * TILEB + r0c * RSZ + ch0 * 16,                      \
                   Ahi + (size_t)(m0 + r0c) * K + kb + ch0 * 8);                \
        CP_ASYNC16(dst + 0 * TILEB + r1c * RSZ + ch1 * 16,                      \
                   Ahi + (size_t)(m0 + r1c) * K + kb + ch1 * 8);                \
        CP_ASYNC16(dst + 1 * TILEB + r0c * RSZ + ch0 * 16,                      \
                   Bhi + (size_t)(n0 + r0c) * K + kb + ch0 * 8);                \
        CP_ASYNC16(dst + 1 * TILEB + r1c * RSZ + ch1 * 16,                      \
                   Bhi + (size_t)(n0 + r1c) * K + kb + ch1 * 8);                \
        CP_COMMIT();                                                            \
    } while (0)

    LOAD_STAGE_H(0);

    for (int c = 0; c < nch; ++c) {
        if (c + 1 < nch) { LOAD_STAGE_H(c + 1); CP_WAIT(1); }
        else             { CP_WAIT(0); }
        __syncthreads();

        const uint32_t s = sb + (c & 1) * STAGE2;
        const uint32_t aHiB = s, bHiB = s + TILEB;

        #pragma unroll
        for (int ks = 0; ks < 2; ++ks) {
            const uint32_t colOff = (uint32_t)(ks * 2 + cA) * 16;
            uint32_t aHi[4][4], bHi[4][2];
            #pragma unroll
            for (int mt = 0; mt < 4; ++mt) {
                uint32_t ad = (uint32_t)(wm * 64 + mt * 16 + rA) * RSZ + colOff;
                LDSM_X4(aHi[mt], aHiB + ad);
            }
            #pragma unroll
            for (int nh = 0; nh < 2; ++nh) {
                uint32_t bd = (uint32_t)(wn * 32 + nh * 16 + rA) * RSZ + colOff;
                uint32_t t[4];
                LDSM_X4(t, bHiB + bd);
                bHi[nh * 2 + 0][0] = t[0]; bHi[nh * 2 + 0][1] = t[2];
                bHi[nh * 2 + 1][0] = t[1]; bHi[nh * 2 + 1][1] = t[3];
            }
            #pragma unroll
            for (int mt = 0; mt < 4; ++mt)
                #pragma unroll
                for (int nt = 0; nt < 4; ++nt)
                    MMA_FP16(acc[mt][nt], aHi[mt], bHi[nt]);
        }
        __syncthreads();
    }

    const int rr = lane >> 2, cc2 = (lane & 3) * 2;
    #pragma unroll
    for (int mt = 0; mt < 4; ++mt) {
        #pragma unroll
        for (int nt = 0; nt < 4; ++nt) {
            int row = m0 + wm * 64 + mt * 16 + rr;
            int col = n0 + wn * 32 + nt * 8 + cc2;
            float b0 = 0.f, b1 = 0.f;
            if (bias) { b0 = bias[col]; b1 = bias[col + 1]; }
            __half2 v0 = __floats2half2_rn(acc[mt][nt][0] + b0, acc[mt][nt][1] + b1);
            __half2 v1 = __floats2half2_rn(acc[mt][nt][2] + b0, acc[mt][nt][3] + b1);
            *(__half2*)&C[(size_t)row * ldc + col] = v0;
            *(__half2*)&C[(size_t)(row + 8) * ldc + col] = v1;
        }
    }
    #undef LOAD_STAGE_H
}

// ---------------------------------------------------------------------------
// Gather-GEMM-scatter (fp16 1-term): rep[m] = concat(flatHi[occ..]) @ Bhi^T,
// then atomicMax into keys[seg[m]] (fmap-encoded).
// ---------------------------------------------------------------------------
__global__ __launch_bounds__(256, 2)
void gemm_gsc_kernel(const __half* __restrict__ flatHi,
                     const __half* __restrict__ Bhi,
                     const int* __restrict__ occ1,
                     const int* __restrict__ occ2,
                     const int* __restrict__ occ3,
                     const int* __restrict__ seg,
                     unsigned* __restrict__ keys, int K) {
    extern __shared__ char smem[];
    const uint32_t sb = smem_u32(smem);
    const int tid = threadIdx.x, lane = tid & 31, wid = tid >> 5;
    const int m0 = blockIdx.y * 128, n0 = blockIdx.x * 128;
    const int wm = wid & 1, wn = wid >> 1;

    float acc[4][4][4];
    #pragma unroll
    for (int i = 0; i < 4; ++i)
        #pragma unroll
        for (int j = 0; j < 4; ++j)
            #pragma unroll
            for (int q = 0; q < 4; ++q) acc[i][j][q] = 0.0f;

    const int nch = K >> 5;
    const int r0c = (2 * tid) >> 2, ch0 = (2 * tid) & 3;
    const int r1c = (2 * tid + 1) >> 2, ch1 = (2 * tid + 1) & 3;
    const int rA = lane & 15;
    const int cA = lane >> 4;

    const int mC0 = (m0 + r0c < MM) ? (m0 + r0c) : (MM - 1);
    const int mC1 = (m0 + r1c < MM) ? (m0 + r1c) : (MM - 1);
    int ia0[3], ia1[3];
    ia0[0] = occ1[mC0]; ia1[0] = occ1[mC1];
    ia0[1] = occ2[mC0]; ia1[1] = occ2[mC1];
    ia0[2] = (K > 1024) ? occ3[mC0] : 0;
    ia1[2] = (K > 1024) ? occ3[mC1] : 0;

    #define LOAD_STAGE_G(cc)                                                    \
    do {                                                                        \
        const int kb = (cc) << 5;                                               \
        const int sg_ = kb >> 9;                                                \
        const int ck = kb & 511;                                                \
        const uint32_t dst = sb + ((cc) & 1) * STAGE2;                          \
        CP_ASYNC16(dst + 0 * TILEB + r0c * RSZ + ch0 * 16,                      \
                   flatHi + (size_t)ia0[sg_] * D2H + ck + ch0 * 8);             \
        CP_ASYNC16(dst + 0 * TILEB + r1c * RSZ + ch1 * 16,                      \
                   flatHi + (size_t)ia1[sg_] * D2H + ck + ch1 * 8);             \
        CP_ASYNC16(dst + 1 * TILEB + r0c * RSZ + ch0 * 16,                      \
                   Bhi + (size_t)(n0 + r0c) * K + kb + ch0 * 8);                \
        CP_ASYNC16(dst + 1 * TILEB + r1c * RSZ + ch1 * 16,                      \
                   Bhi + (size_t)(n0 + r1c) * K + kb + ch1 * 8);                \
        CP_COMMIT();                                                            \
    } while (0)

    LOAD_STAGE_G(0);

    for (int c = 0; c < nch; ++c) {
        if (c + 1 < nch) { LOAD_STAGE_G(c + 1); CP_WAIT(1); }
        else             { CP_WAIT(0); }
        __syncthreads();

        const uint32_t s = sb + (c & 1) * STAGE2;
        const uint32_t aHiB = s, bHiB = s + TILEB;

        #pragma unroll
        for (int ks = 0; ks < 2; ++ks) {
            const uint32_t colOff = (uint32_t)(ks * 2 + cA) * 16;
            uint32_t aHi[4][4], bHi[4][2];
            #pragma unroll
            for (int mt = 0; mt < 4; ++mt) {
                uint32_t ad = (uint32_t)(wm * 64 + mt * 16 + rA) * RSZ + colOff;
                LDSM_X4(aHi[mt], aHiB + ad);
            }
            #pragma unroll
            for (int nh = 0; nh < 2; ++nh) {
                uint32_t bd = (uint32_t)(wn * 32 + nh * 16 + rA) * RSZ + colOff;
                uint32_t t[4];
                LDSM_X4(t, bHiB + bd);
                bHi[nh * 2 + 0][0] = t[0]; bHi[nh * 2 + 0][1] = t[2];
                bHi[nh * 2 + 1][0] = t[1]; bHi[nh * 2 + 1][1] = t[3];
            }
            #pragma unroll
            for (int mt = 0; mt < 4; ++mt)
                #pragma unroll
                for (int nt = 0; nt < 4; ++nt)
                    MMA_FP16(acc[mt][nt], aHi[mt], bHi[nt]);
        }
        __syncthreads();
    }

    // ---- epilogue: fmap + atomicMax scatter into segment keys ----
    const int rr = lane >> 2, cc2 = (lane & 3) * 2;
    #pragma unroll
    for (int mt = 0; mt < 4; ++mt) {
        int rowL = wm * 64 + mt * 16 + rr;
        int mA = m0 + rowL, mB = mA + 8;
        int sgA = (mA < MM) ? seg[mA] : -1;
        int sgB = (mB < MM) ? seg[mB] : -1;
        #pragma unroll
        for (int nt = 0; nt < 4; ++nt) {
            int col = n0 + wn * 32 + nt * 8 + cc2;
            if (sgA >= 0) {
                unsigned* d = keys + (size_t)sgA * D2H + col;
                atomicMax(d,     fmap(acc[mt][nt][0]));
                atomicMax(d + 1, fmap(acc[mt][nt][1]));
            }
            if (sgB >= 0) {
                unsigned* d = keys + (size_t)sgB * D2H + col;
                atomicMax(d,     fmap(acc[mt][nt][2]));
                atomicMax(d + 1, fmap(acc[mt][nt][3]));
            }
        }
    }
    #undef LOAD_STAGE_G
}

// ---------------------------------------------------------------------------
// Pack kernels
// ---------------------------------------------------------------------------
__global__ void convert_pad_kernel(const float* __restrict__ src,
                                   __half* __restrict__ hi,
                                   int rows, int sk, int dk) {
    size_t total = (size_t)rows * dk;
    for (size_t idx = blockIdx.x * (size_t)blockDim.x + threadIdx.x; idx < total;
         idx += (size_t)gridDim.x * blockDim.x) {
        int r = (int)(idx / dk), c = (int)(idx % dk);
        float f = (c < sk) ? src[(size_t)r * sk + c] : 0.0f;
        hi[idx] = __float2half(f);
    }
}

__global__ void pack_wih_kernel(const float* __restrict__ wih,
                                const float* __restrict__ b,
                                __half* __restrict__ hi,
                                float* __restrict__ pb) {
    const int total = G4 * EP;
    for (int idx = blockIdx.x * blockDim.x + threadIdx.x; idx < total;
         idx += gridDim.x * blockDim.x) {
        int rp = idx / EP, k = idx % EP;
        int j = rp >> 2, g = rp & 3;
        float f = (k < EE) ? wih[(size_t)(g * 256 + j) * EE + k] : 0.0f;
        hi[idx] = __float2half(f);
        if (k == 0) pb[rp] = b[g * 256 + j];
    }
}

__global__ void pack_whh_kernel(const float* __restrict__ whh,
                                __half* __restrict__ hi,
                                __half* __restrict__ lo) {
    const int total = G4 * HH;
    for (int idx = blockIdx.x * blockDim.x + threadIdx.x; idx < total;
         idx += gridDim.x * blockDim.x) {
        int rp = idx >> 8, k = idx & 255;
        int j = rp >> 2, g = rp & 3;
        float v = whh[(size_t)(g * 256 + j) * HH + k];
        __half h, l; splith(v, h, l);
        hi[idx] = h; lo[idx] = l;
    }
}

__global__ void pack_pairWT_kernel(const float* __restrict__ pair_hW,
                                   __half* __restrict__ hi) {
    const int total = 3 * D2H * G4;
    for (int idx = blockIdx.x * blockDim.x + threadIdx.x; idx < total;
         idx += gridDim.x * blockDim.x) {
        int k = idx / (D2H * G4);
        int rem = idx - k * (D2H * G4);
        int n = rem >> 10, kk = rem & 1023;
        hi[idx] = __float2half(pair_hW[(size_t)k * (G4 * D2H) + (size_t)kk * D2H + n]);
    }
}

__global__ void pack_triWT_kernel(const float* __restrict__ tri_hW,
                                  __half* __restrict__ hi) {
    const int total = D2H * 1536;
    for (int idx = blockIdx.x * blockDim.x + threadIdx.x; idx < total;
         idx += gridDim.x * blockDim.x) {
        int n = idx / 1536, kk = idx % 1536;
        hi[idx] = __float2half(tri_hW[(size_t)kk * D2H + n]);
    }
}

__global__ void pack_allWT_kernel(const float* __restrict__ all_hW,
                                  __half* __restrict__ hi) {
    const int total = D2H * 2048;
    for (int idx = blockIdx.x * blockDim.x + threadIdx.x; idx < total;
         idx += gridDim.x * blockDim.x) {
        int n = idx >> 11, k = idx & 2047;
        hi[idx] = __float2half(all_hW[(size_t)k * D2H + n]);
    }
}

__global__ void zero_keys_kernel(unsigned* __restrict__ pk, unsigned* __restrict__ tk) {
    const size_t np = (size_t)3 * CC * D2H;
    const size_t nt = (size_t)CC * D2H;
    for (size_t i = blockIdx.x * (size_t)blockDim.x + threadIdx.x; i < np + nt;
         i += (size_t)gridDim.x * blockDim.x) {
        if (i < np) pk[i] = 0u; else tk[i - np] = 0u;
    }
}

// ---------------------------------------------------------------------------
// Persistent HMMA BiLSTM recurrence (fp16 3-term; 8-CTA group barriers,
// Gx(fp16) prefetched at step start).
// ---------------------------------------------------------------------------
#define PRSZ   528
#define LP_AHI 0
#define LP_ALO 16896
#define LP_BHI 33792
#define LP_BLO 101376
#define SMEM_LSTMP 168960

__global__ __launch_bounds__(256, 1)
void lstm_persist_kernel(const __half* __restrict__ GxF,
                         const __half* __restrict__ GxB,
                         const __half* __restrict__ whhHiF,
                         const __half* __restrict__ whhLoF,
                         const __half* __restrict__ whhHiB,
                         const __half* __restrict__ whhLoB,
                         __half* __restrict__ flatHi,
                         __half* __restrict__ flatLo) {
    extern __shared__ char smem[];
    const uint32_t sb = smem_u32(smem);
    const int tid = threadIdx.x, lane = tid & 31, wid = tid >> 5;
    const int dir = blockIdx.z;
    const int p0 = blockIdx.x * 32;
    const int c0 = blockIdx.y * 128;
    const int hcol = dir * HH;
    const int bidx = dir * 8 + blockIdx.x;
    const __half* Gx = dir ? GxB : GxF;
    const __half* Whi = dir ? whhHiB : whhHiF;
    const __half* Wlo = dir ? whhLoB : whhLoF;

    for (int ch = tid; ch < 128 * 32; ch += 256) {
        int row = ch >> 5, cb = ch & 31;
        size_t src = (size_t)(c0 + row) * HH + cb * 8;
        CP_ASYNC16(sb + LP_BHI + row * PRSZ + cb * 16, Whi + src);
        CP_ASYNC16(sb + LP_BLO + row * PRSZ + cb * 16, Wlo + src);
    }
    CP_COMMIT(); CP_WAIT(0);
    __syncthreads();

    float creg[2][2] = {{0.f, 0.f}, {0.f, 0.f}};
    const int rr = lane >> 2, cc2 = (lane & 3) * 2;
    const bool evenT = ((lane & 1) == 0);

    for (int s = 0; s < TT; ++s) {
        const int tcur = dir ? (TT - 1 - s) : s;

        // ---- prefetch Gx (fp16) for this step
        float2 gpre[2][2][2];
        #pragma unroll
        for (int mt = 0; mt < 2; ++mt) {
            #pragma unroll
            for (int nt = 0; nt < 2; ++nt) {
                int prow = p0 + mt * 16 + rr;
                int col = c0 + wid * 16 + nt * 8 + cc2;
                size_t n0i = (size_t)tcur * PP + prow;
                gpre[mt][nt][0] = __half22float2(*(const __half2*)&Gx[n0i * G4 + col]);
                gpre[mt][nt][1] = __half22float2(*(const __half2*)&Gx[(n0i + 8) * G4 + col]);
            }
        }

        float acc[2][2][4];
        #pragma unroll
        for (int i = 0; i < 2; ++i)
            #pragma unroll
            for (int j = 0; j < 2; ++j)
                #pragma unroll
                for (int q = 0; q < 4; ++q) acc[i][j][q] = 0.0f;

        if (s > 0) {
            group_barrier(bidx, tid, 8u);

            const int nprev = dir ? (tcur + 1) : (tcur - 1);
            for (int ch = tid; ch < 32 * 32; ch += 256) {
                int row = ch >> 5, cb = ch & 31;
                size_t src = (size_t)(nprev * PP + p0 + row) * D2H + hcol + cb * 8;
                CP_ASYNC16(sb + LP_AHI + row * PRSZ + cb * 16, flatHi + src);
                CP_ASYNC16(sb + LP_ALO + row * PRSZ + cb * 16, flatLo + src);
            }
            CP_COMMIT(); CP_WAIT(0);
            __syncthreads();

            #pragma unroll 4
            for (int kc = 0; kc < 16; ++kc) {
                const uint32_t colOff = (uint32_t)kc * 32 + (uint32_t)(lane >> 4) * 16;
                uint32_t aHi[2][4], bHi[2][2];
                #pragma unroll
                for (int mt = 0; mt < 2; ++mt) {
                    uint32_t ad = (uint32_t)(mt * 16 + (lane & 15)) * PRSZ + colOff;
                    LDSM_X4(aHi[mt], sb + LP_AHI + ad);
                }
                {
                    uint32_t bd = (uint32_t)(wid * 16 + (lane & 15)) * PRSZ + colOff;
                    uint32_t t[4];
                    LDSM_X4(t, sb + LP_BHI + bd);
                    bHi[0][0] = t[0]; bHi[0][1] = t[2];
                    bHi[1][0] = t[1]; bHi[1][1] = t[3];
                }
                #pragma unroll
                for (int mt = 0; mt < 2; ++mt)
                    #pragma unroll
                    for (int nt = 0; nt < 2; ++nt)
                        MMA_FP16(acc[mt][nt], aHi[mt], bHi[nt]);
                {
                    uint32_t aLo[2][4];
                    #pragma unroll
                    for (int mt = 0; mt < 2; ++mt) {
                        uint32_t ad = (uint32_t)(mt * 16 + (lane & 15)) * PRSZ + colOff;
                        LDSM_X4(aLo[mt], sb + LP_ALO + ad);
                    }
                    #pragma unroll
                    for (int mt = 0; mt < 2; ++mt)
                        #pragma unroll
                        for (int nt = 0; nt < 2; ++nt)
                            MMA_FP16(acc[mt][nt], aLo[mt], bHi[nt]);
                }
                {
                    uint32_t bLo[2][2];
                    uint32_t bd = (uint32_t)(wid * 16 + (lane & 15)) * PRSZ + colOff;
                    uint32_t t[4];
                    LDSM_X4(t, sb + LP_BLO + bd);
                    bLo[0][0] = t[0]; bLo[0][1] = t[2];
                    bLo[1][0] = t[1]; bLo[1][1] = t[3];
                    #pragma unroll
                    for (int mt = 0; mt < 2; ++mt)
                        #pragma unroll
                        for (int nt = 0; nt < 2; ++nt)
                            MMA_FP16(acc[mt][nt], aHi[mt], bLo[nt]);
                }
            }
        }

        #pragma unroll
        for (int mt = 0; mt < 2; ++mt) {
            #pragma unroll
            for (int nt = 0; nt < 2; ++nt) {
                int prow = p0 + mt * 16 + rr;
                int col = c0 + wid * 16 + nt * 8 + cc2;
                int j = col >> 2;
                float2 g0 = gpre[mt][nt][0];
                float2 g1 = gpre[mt][nt][1];
                float v0 = acc[mt][nt][0] + g0.x;
                float v1 = acc[mt][nt][1] + g0.y;
                float v2 = acc[mt][nt][2] + g1.x;
                float v3 = acc[mt][nt][3] + g1.y;
                float w0 = __shfl_xor_sync(0xffffffffu, v0, 1);
                float w1 = __shfl_xor_sync(0xffffffffu, v1, 1);
                float w2 = __shfl_xor_sync(0xffffffffu, v2, 1);
                float w3 = __shfl_xor_sync(0xffffffffu, v3, 1);
                float I, F, G, O;
                int p;
                if (evenT) { I = v0; F = v1; G = w0; O = w1; p = prow; }
                else       { I = w2; F = w3; G = v2; O = v3; p = prow + 8; }
                float cold = creg[mt][nt];
                float cn = sigmoidf_(F) * cold + sigmoidf_(I) * tanhf(G);
                float h = sigmoidf_(O) * tanhf(cn);
                creg[mt][nt] = cn;
                size_t nn = (size_t)tcur * PP + p;
                __half hh, hl; splith(h, hh, hl);
                flatHi[nn * D2H + hcol + j] = hh;
                flatLo[nn * D2H + hcol + j] = hl;
            }
        }
        __syncthreads();
    }
}

// ---------------------------------------------------------------------------
// Finalize kernels
// ---------------------------------------------------------------------------
__global__ __launch_bounds__(256)
void pair_final_kernel(const unsigned* __restrict__ keys,
                       const float* __restrict__ hb,
                       const float* __restrict__ backoff,
                       const float* __restrict__ oW,
                       const float* __restrict__ ob,
                       float* __restrict__ pv, float* __restrict__ out) {
    const int b = blockIdx.x;
    const int k = b >> 14;
    const unsigned* src = keys + (size_t)b * D2H;
    float partial = 0.0f;
    #pragma unroll
    for (int it = 0; it < 2; ++it) {
        int c = threadIdx.x + it * 256;
        unsigned u = src[c];
        float val = u ? (funmap(u) + hb[k * D2H + c]) : backoff[k * D2H + c];
        float t = tanhf(val);
        pv[(size_t)b * D2H + c] = t;
        partial += t * oW[k * D2H + c];
    }
    float tot = blockReduceSum256(partial);
    if (threadIdx.x == 0) out[CC + b] = tot + ob[k];
}

__global__ __launch_bounds__(256)
void tri_final_kernel(const unsigned* __restrict__ keys,
                      const float* __restrict__ hb,
                      const float* __restrict__ backoff,
                      float* __restrict__ tv) {
    const int s = blockIdx.x;
    const unsigned* src = keys + (size_t)s * D2H;
    #pragma unroll
    for (int it = 0; it < 2; ++it) {
        int c = threadIdx.x + it * 256;
        unsigned u = src[c];
        float val = u ? (funmap(u) + hb[c]) : backoff[c];
        tv[(size_t)s * D2H + c] = tanhf(val);
    }
}

// gather 8H features (fp16 hi only)
__global__ void gather_feats_kernel(const float* __restrict__ pv,
                                    const float* __restrict__ tv,
                                    const int* __restrict__ tpi,
                                    __half* __restrict__ fhi) {
    const int s = blockIdx.x;
    const int i0 = tpi[s * 3 + 0];
    const int i1 = tpi[s * 3 + 1];
    const int i2 = tpi[s * 3 + 2];
    for (int j = threadIdx.x; j < 2048; j += blockDim.x) {
        int q = j >> 9, c = j & 511;
        float v;
        if (q == 0)      v = pv[((size_t)2 * CC + i0) * D2H + c];
        else if (q == 1) v = pv[((size_t)1 * CC + i1) * D2H + c];
        else if (q == 2) v = pv[(size_t)i2 * D2H + c];
        else             v = tv[(size_t)s * D2H + c];
        fhi[(size_t)s * 2048 + j] = __float2half(v);
    }
}

__global__ __launch_bounds__(256)
void triple_logit_kernel(const float* __restrict__ fin,
                         const float* __restrict__ tW,
                         const float* __restrict__ tb,
                         float* __restrict__ out) {
    const int s = blockIdx.x;
    float partial = 0.0f;
    #pragma unroll
    for (int it = 0; it < 2; ++it) {
        int c = threadIdx.x + it * 256;
        float v = fin[(size_t)s * D2H + c];
        v = v > 0.0f ? v : 0.0f;
        partial += v * tW[c];
    }
    float tot = blockReduceSum256(partial);
    if (threadIdx.x == 0) out[s] = tot + tb[0];
}

// ---------------------------------------------------------------------------
// Launcher
// ---------------------------------------------------------------------------
extern "C" void kernel_launch(void* const* d_in, const int* in_sizes, int n_in,
                              void* d_out, int out_size) {
    const float* x        = (const float*)d_in[0];
    const float* wih_f    = (const float*)d_in[1];
    const float* whh_f    = (const float*)d_in[2];
    const float* b_f      = (const float*)d_in[3];
    const float* wih_b    = (const float*)d_in[4];
    const float* whh_b    = (const float*)d_in[5];
    const float* b_b      = (const float*)d_in[6];
    const float* pair_hW  = (const float*)d_in[7];
    const float* pair_hb  = (const float*)d_in[8];
    const float* pair_oW  = (const float*)d_in[9];
    const float* pair_ob  = (const float*)d_in[10];
    const float* pair_bo  = (const float*)d_in[11];
    const float* tri_hW   = (const float*)d_in[12];
    const float* tri_hb   = (const float*)d_in[13];
    const float* tri_bo   = (const float*)d_in[14];
    const float* all_hW   = (const float*)d_in[15];
    const float* all_hb   = (const float*)d_in[16];
    const float* out_tW   = (const float*)d_in[17];
    const float* out_tb   = (const float*)d_in[18];
    const int*   occ1     = (const int*)d_in[19];
    const int*   occ2     = (const int*)d_in[20];
    const int*   seg      = (const int*)d_in[21];
    const int*   tri_o1   = (const int*)d_in[22];
    const int*   tri_o2   = (const int*)d_in[23];
    const int*   tri_o3   = (const int*)d_in[24];
    const int*   tri_seg  = (const int*)d_in[25];
    const int*   tri_pi   = (const int*)d_in[26];
    float* out = (float*)d_out;

    float *pv, *tv, *fin, *pbF, *pbB;
    unsigned *pk, *tk;
    __half *GxF, *GxB;
    __half *xHi, *wHiF, *wHiB, *flHi, *flLo;
    __half *whF, *wlF, *whB, *wlB;
    __half *pwHi, *twHi, *awHi, *ftHi;
    cudaGetSymbolAddress((void**)&GxF,  g_GxF);
    cudaGetSymbolAddress((void**)&GxB,  g_GxB);
    cudaGetSymbolAddress((void**)&pk,   g_pairKeys);
    cudaGetSymbolAddress((void**)&tk,   g_triKeys);
    cudaGetSymbolAddress((void**)&pv,   g_pv);
    cudaGetSymbolAddress((void**)&tv,   g_tv);
    cudaGetSymbolAddress((void**)&fin,  g_final);
    cudaGetSymbolAddress((void**)&pbF,  g_pbF);
    cudaGetSymbolAddress((void**)&pbB,  g_pbB);
    cudaGetSymbolAddress((void**)&xHi,  g_xHi);
    cudaGetSymbolAddress((void**)&wHiF, g_wHiF);
    cudaGetSymbolAddress((void**)&wHiB, g_wHiB);
    cudaGetSymbolAddress((void**)&whF,  g_whhHiF);
    cudaGetSymbolAddress((void**)&wlF,  g_whhLoF);
    cudaGetSymbolAddress((void**)&whB,  g_whhHiB);
    cudaGetSymbolAddress((void**)&wlB,  g_whhLoB);
    cudaGetSymbolAddress((void**)&flHi, g_flatHi);
    cudaGetSymbolAddress((void**)&flLo, g_flatLo);
    cudaGetSymbolAddress((void**)&pwHi, g_pwHi);
    cudaGetSymbolAddress((void**)&twHi, g_twHi);
    cudaGetSymbolAddress((void**)&awHi, g_aWHi);
    cudaGetSymbolAddress((void**)&ftHi, g_ftHi);

    cudaFuncSetAttribute(gemm_fp16x1_kernel,
                         cudaFuncAttributeMaxDynamicSharedMemorySize, SMEM_G1);
    cudaFuncSetAttribute(gemm_fp16x1h_kernel,
                         cudaFuncAttributeMaxDynamicSharedMemorySize, SMEM_G1);
    cudaFuncSetAttribute(gemm_gsc_kernel,
                         cudaFuncAttributeMaxDynamicSharedMemorySize, SMEM_G1);
    cudaFuncSetAttribute(lstm_persist_kernel,
                         cudaFuncAttributeMaxDynamicSharedMemorySize, SMEM_LSTMP);

    // 1) convert/pack operands (fp16)
    convert_pad_kernel<<<4096, 256>>>(x, xHi, NPOS, EE, EP);
    pack_wih_kernel<<<512, 256>>>(wih_f, b_f, wHiF, pbF);
    pack_wih_kernel<<<512, 256>>>(wih_b, b_b, wHiB, pbB);
    pack_whh_kernel<<<512, 256>>>(whh_f, whF, wlF);
    pack_whh_kernel<<<512, 256>>>(whh_b, whB, wlB);
    pack_pairWT_kernel<<<3072, 256>>>(pair_hW, pwHi);
    pack_triWT_kernel<<<1536, 256>>>(tri_hW, twHi);
    pack_allWT_kernel<<<1024, 256>>>(all_hW, awHi);

    // 2) input projections (gate-permuted cols): Gx(fp16) = xHi @ wihHi^T + pb
    gemm_fp16x1h_kernel<<<dim3(8, 512), 256, SMEM_G1>>>(xHi, wHiF, pbF, GxF, EP);
    gemm_fp16x1h_kernel<<<dim3(8, 512), 256, SMEM_G1>>>(xHi, wHiB, pbB, GxB, EP);

    // 3) zero segment-max keys
    zero_keys_kernel<<<32768, 256>>>(pk, tk);

    // 4) BiLSTM recurrence: persistent HMMA kernel (fp16 3-term)
    lstm_persist_kernel<<<dim3(8, 8, 2), 256, SMEM_LSTMP>>>(
        GxF, GxB, whF, wlF, whB, wlB, flHi, flLo);

    // 5) gather-GEMM-scatter: pair types + triples (fp16 1-term)
    for (int k = 0; k < 3; ++k)
        gemm_gsc_kernel<<<dim3(4, MTILES), 256, SMEM_G1>>>(
            flHi, pwHi + (size_t)k * D2H * G4,
            occ1 + k * MM, occ2 + k * MM, occ1 + k * MM,
            seg + k * MM, pk + (size_t)k * CC * D2H, G4);
    gemm_gsc_kernel<<<dim3(4, MTILES), 256, SMEM_G1>>>(
        flHi, twHi, tri_o1, tri_o2, tri_o3, tri_seg, tk, 1536);

    // 6) finalize pooled vectors (+ pair logits)
    pair_final_kernel<<<3 * CC, 256>>>(pk, pair_hb, pair_bo, pair_oW, pair_ob, pv, out);
    tri_final_kernel<<<CC, 256>>>(tk, tri_hb, tri_bo, tv);

    // 7) final MLP + triple logits (fp16 1-term, contiguous ftHi)
    gather_feats_kernel<<<CC, 256>>>(pv, tv, tri_pi, ftHi);
    gemm_fp16x1_kernel<<<dim3(D2H / 128, CC / 128), 256, SMEM_G1>>>(
        ftHi, awHi, all_hb, fin, 2048);
    triple_logit_kernel<<<CC, 256>>>(fin, out_tW, out_tb, out);
}

// round 15
// speedup vs baseline: 1.0331x; 1.0331x over previous
#include <cuda_runtime.h>
#include <cuda_fp16.h>
#include <math.h>
#include <stdint.h>

// ---------------------------------------------------------------------------
// Problem constants
// ---------------------------------------------------------------------------
#define TT   256
#define PP   256
#define EE   300
#define HH   256
#define NPOS 65536            // T*P
#define G4   1024             // 4H
#define G8   2048             // both directions
#define D2H  512              // 2H
#define MM   50000
#define CC   16384
#define EP   320              // E padded to multiple of 32
#define MTILES ((MM + 127) / 128)   // 391

// ---------------------------------------------------------------------------
// Device scratch (static allocations only)
// ---------------------------------------------------------------------------
__device__ float    g_Gx[(size_t)NPOS * G8];           // 536 MB fp32, F|B halves
__device__ unsigned g_pairKeys[(size_t)3 * CC * D2H];  // 100 MB
__device__ unsigned g_triKeys[(size_t)CC * D2H];       // 33 MB
__device__ float    g_pv[(size_t)3 * CC * D2H];        // 100 MB
__device__ float    g_tv[(size_t)CC * D2H];            // 33 MB
__device__ float    g_final[(size_t)CC * D2H];         // 33 MB
__device__ float    g_pb[G8];                          // permuted biases F|B
__device__ unsigned g_barCnt[16];                      // per (dir,ptile) barrier
__device__ unsigned g_barGen[16];

// fp16 operand buffers
__device__ __half g_xHi[(size_t)NPOS * EP];            // 42 MB (hi only)
__device__ __half g_wHi[(size_t)G8 * EP];              // packed rows (dir,j*4+g)
__device__ __half g_whhHiF[(size_t)G4 * HH];           // packed rows j*4+g
__device__ __half g_whhLoF[(size_t)G4 * HH];
__device__ __half g_whhHiB[(size_t)G4 * HH];
__device__ __half g_whhLoB[(size_t)G4 * HH];
__device__ __half g_flatHi[(size_t)NPOS * D2H];        // 67 MB
__device__ __half g_flatLo[(size_t)NPOS * D2H];        // used by LSTM only
__device__ __half g_pwHi[(size_t)3 * D2H * G4];        // pairWT [3][512][1024]
__device__ __half g_twHi[(size_t)D2H * 1536];          // triWT [512][1536]
__device__ __half g_aWHi[(size_t)D2H * 2048];
__device__ __half g_ftHi[(size_t)CC * 2048];           // 67 MB (hi only)

// ---------------------------------------------------------------------------
// Helpers
// ---------------------------------------------------------------------------
__device__ __forceinline__ uint32_t smem_u32(const void* p) {
    uint32_t a;
    asm("{ .reg .u64 t; cvta.to.shared.u64 t, %1; cvt.u32.u64 %0, t; }"
        : "=r"(a) : "l"(p));
    return a;
}

#define LDSM_X4(r, addr) \
    asm volatile("ldmatrix.sync.aligned.m8n8.x4.shared.b16 {%0,%1,%2,%3}, [%4];" \
        : "=r"((r)[0]), "=r"((r)[1]), "=r"((r)[2]), "=r"((r)[3]) : "r"(addr))

#define MMA_FP16(d, a, b) \
    asm volatile("mma.sync.aligned.m16n8k16.row.col.f32.f16.f16.f32 " \
        "{%0,%1,%2,%3}, {%4,%5,%6,%7}, {%8,%9}, {%0,%1,%2,%3};" \
        : "+f"((d)[0]), "+f"((d)[1]), "+f"((d)[2]), "+f"((d)[3]) \
        : "r"((a)[0]), "r"((a)[1]), "r"((a)[2]), "r"((a)[3]), \
          "r"((b)[0]), "r"((b)[1]))

#define CP_ASYNC16(dst, src) \
    asm volatile("cp.async.cg.shared.global [%0], [%1], 16;" \
                 :: "r"(dst), "l"(src))
#define CP_COMMIT() asm volatile("cp.async.commit_group;" ::: "memory")
#define CP_WAIT(n)  asm volatile("cp.async.wait_group %0;" :: "n"(n) : "memory")

__device__ __forceinline__ float sigmoidf_(float x) { return 1.0f / (1.0f + expf(-x)); }

__device__ __forceinline__ unsigned fmap(float f) {
    unsigned b = __float_as_uint(f);
    return (b & 0x80000000u) ? ~b : (b | 0x80000000u);
}
__device__ __forceinline__ float funmap(unsigned u) {
    return (u & 0x80000000u) ? __uint_as_float(u & 0x7FFFFFFFu)
                             : __uint_as_float(~u);
}
__device__ __forceinline__ float warpReduceSum(float v) {
    #pragma unroll
    for (int o = 16; o > 0; o >>= 1) v += __shfl_down_sync(0xffffffffu, v, o);
    return v;
}
__device__ __forceinline__ float blockReduceSum256(float v) {
    __shared__ float sh[8];
    int lane = threadIdx.x & 31, wid = threadIdx.x >> 5;
    v = warpReduceSum(v);
    if (lane == 0) sh[wid] = v;
    __syncthreads();
    v = (threadIdx.x < 8) ? sh[threadIdx.x] : 0.0f;
    if (wid == 0) v = warpReduceSum(v);
    return v;
}
__device__ __forceinline__ void splith(float f, __half& h, __half& l) {
    h = __float2half(f);
    l = __float2half(f - __half2float(h));
}

// per-(dir,ptile) group barrier
__device__ __forceinline__ void group_barrier(int bidx, int tid, unsigned nCTA) {
    __syncthreads();
    if (tid == 0) {
        __threadfence();
        unsigned gen = atomicAdd(&g_barGen[bidx], 0u);
        unsigned prev = atomicAdd(&g_barCnt[bidx], 1u);
        if (prev == nCTA - 1u) {
            atomicExch(&g_barCnt[bidx], 0u);
            __threadfence();
            atomicAdd(&g_barGen[bidx], 1u);
        } else {
            while (atomicAdd(&g_barGen[bidx], 0u) == gen) { __nanosleep(32); }
        }
        __threadfence();
    }
    __syncthreads();
}

// ---------------------------------------------------------------------------
// Shared GEMM tile constants
// ---------------------------------------------------------------------------
#define RSZ   80
#define TILEB (128 * RSZ)       // 10240
#define STAGE2 (2 * TILEB)      // 20480 (Ahi, Bhi)
#define SMEM_G1 (2 * STAGE2)    // 40960

// ---------------------------------------------------------------------------
// fp16 1-term GEMM, fp32 output: C[M,N] = Ahi @ Bhi^T + bias
// CTA tile 128x128, 256 threads (8 warps: 2 M x 4 N; warp tile 64x32).
// ---------------------------------------------------------------------------
__global__ __launch_bounds__(256, 2)
void gemm_fp16x1_kernel(const __half* __restrict__ Ahi,
                        const __half* __restrict__ Bhi,
                        const float* __restrict__ bias,
                        float* __restrict__ C, int K) {
    extern __shared__ char smem[];
    const uint32_t sb = smem_u32(smem);
    const int tid = threadIdx.x, lane = tid & 31, wid = tid >> 5;
    const int m0 = blockIdx.y * 128, n0 = blockIdx.x * 128;
    const int ldc = gridDim.x * 128;
    const int wm = wid & 1, wn = wid >> 1;

    float acc[4][4][4];
    #pragma unroll
    for (int i = 0; i < 4; ++i)
        #pragma unroll
        for (int j = 0; j < 4; ++j)
            #pragma unroll
            for (int q = 0; q < 4; ++q) acc[i][j][q] = 0.0f;

    const int nch = K >> 5;
    const int r0c = (2 * tid) >> 2, ch0 = (2 * tid) & 3;
    const int r1c = (2 * tid + 1) >> 2, ch1 = (2 * tid + 1) & 3;
    const int rA = lane & 15;
    const int cA = lane >> 4;

    #define LOAD_STAGE(cc)                                                      \
    do {                                                                        \
        const int kb = (cc) << 5;                                               \
        const uint32_t dst = sb + ((cc) & 1) * STAGE2;                          \
        CP_ASYNC16(dst + 0 * TILEB + r0c * RSZ + ch0 * 16,                      \
                   Ahi + (size_t)(m0 + r0c) * K + kb + ch0 * 8);                \
        CP_ASYNC16(dst + 0 * TILEB + r1c * RSZ + ch1 * 16,                      \
                   Ahi + (size_t)(m0 + r1c) * K + kb + ch1 * 8);                \
        CP_ASYNC16(dst + 1 * TILEB + r0c * RSZ + ch0 * 16,                      \
                   Bhi + (size_t)(n0 + r0c) * K + kb + ch0 * 8);                \
        CP_ASYNC16(dst + 1 * TILEB + r1c * RSZ + ch1 * 16,                      \
                   Bhi + (size_t)(n0 + r1c) * K + kb + ch1 * 8);                \
        CP_COMMIT();                                                            \
    } while (0)

    LOAD_STAGE(0);

    for (int c = 0; c < nch; ++c) {
        if (c + 1 < nch) { LOAD_STAGE(c + 1); CP_WAIT(1); }
        else             { CP_WAIT(0); }
        __syncthreads();

        const uint32_t s = sb + (c & 1) * STAGE2;
        const uint32_t aHiB = s, bHiB = s + TILEB;

        #pragma unroll
        for (int ks = 0; ks < 2; ++ks) {
            const uint32_t colOff = (uint32_t)(ks * 2 + cA) * 16;
            uint32_t aHi[4][4], bHi[4][2];
            #pragma unroll
            for (int mt = 0; mt < 4; ++mt) {
                uint32_t ad = (uint32_t)(wm * 64 + mt * 16 + rA) * RSZ + colOff;
                LDSM_X4(aHi[mt], aHiB + ad);
            }
            #pragma unroll
            for (int nh = 0; nh < 2; ++nh) {
                uint32_t bd = (uint32_t)(wn * 32 + nh * 16 + rA) * RSZ + colOff;
                uint32_t t[4];
                LDSM_X4(t, bHiB + bd);
                bHi[nh * 2 + 0][0] = t[0]; bHi[nh * 2 + 0][1] = t[2];
                bHi[nh * 2 + 1][0] = t[1]; bHi[nh * 2 + 1][1] = t[3];
            }
            #pragma unroll
            for (int mt = 0; mt < 4; ++mt)
                #pragma unroll
                for (int nt = 0; nt < 4; ++nt)
                    MMA_FP16(acc[mt][nt], aHi[mt], bHi[nt]);
        }
        __syncthreads();
    }

    const int rr = lane >> 2, cc2 = (lane & 3) * 2;
    #pragma unroll
    for (int mt = 0; mt < 4; ++mt) {
        #pragma unroll
        for (int nt = 0; nt < 4; ++nt) {
            int row = m0 + wm * 64 + mt * 16 + rr;
            int col = n0 + wn * 32 + nt * 8 + cc2;
            float b0 = 0.f, b1 = 0.f;
            if (bias) { b0 = bias[col]; b1 = bias[col + 1]; }
            float2 v0 = make_float2(acc[mt][nt][0] + b0, acc[mt][nt][1] + b1);
            float2 v1 = make_float2(acc[mt][nt][2] + b0, acc[mt][nt][3] + b1);
            *(float2*)&C[(size_t)row * ldc + col] = v0;
            *(float2*)&C[(size_t)(row + 8) * ldc + col] = v1;
        }
    }
    #undef LOAD_STAGE
}

// ---------------------------------------------------------------------------
// Gather-GEMM-scatter (fp16 1-term): rep[m] = concat(flatHi[occ..]) @ Bhi^T,
// then atomicMax into keys[seg[m]] (fmap-encoded).
// ---------------------------------------------------------------------------
__global__ __launch_bounds__(256, 2)
void gemm_gsc_kernel(const __half* __restrict__ flatHi,
                     const __half* __restrict__ Bhi,
                     const int* __restrict__ occ1,
                     const int* __restrict__ occ2,
                     const int* __restrict__ occ3,
                     const int* __restrict__ seg,
                     unsigned* __restrict__ keys, int K) {
    extern __shared__ char smem[];
    const uint32_t sb = smem_u32(smem);
    const int tid = threadIdx.x, lane = tid & 31, wid = tid >> 5;
    const int m0 = blockIdx.y * 128, n0 = blockIdx.x * 128;
    const int wm = wid & 1, wn = wid >> 1;

    float acc[4][4][4];
    #pragma unroll
    for (int i = 0; i < 4; ++i)
        #pragma unroll
        for (int j = 0; j < 4; ++j)
            #pragma unroll
            for (int q = 0; q < 4; ++q) acc[i][j][q] = 0.0f;

    const int nch = K >> 5;
    const int r0c = (2 * tid) >> 2, ch0 = (2 * tid) & 3;
    const int r1c = (2 * tid + 1) >> 2, ch1 = (2 * tid + 1) & 3;
    const int rA = lane & 15;
    const int cA = lane >> 4;

    const int mC0 = (m0 + r0c < MM) ? (m0 + r0c) : (MM - 1);
    const int mC1 = (m0 + r1c < MM) ? (m0 + r1c) : (MM - 1);
    int ia0[3], ia1[3];
    ia0[0] = occ1[mC0]; ia1[0] = occ1[mC1];
    ia0[1] = occ2[mC0]; ia1[1] = occ2[mC1];
    ia0[2] = (K > 1024) ? occ3[mC0] : 0;
    ia1[2] = (K > 1024) ? occ3[mC1] : 0;

    #define LOAD_STAGE_G(cc)                                                    \
    do {                                                                        \
        const int kb = (cc) << 5;                                               \
        const int sg_ = kb >> 9;                                                \
        const int ck = kb & 511;                                                \
        const uint32_t dst = sb + ((cc) & 1) * STAGE2;                          \
        CP_ASYNC16(dst + 0 * TILEB + r0c * RSZ + ch0 * 16,                      \
                   flatHi + (size_t)ia0[sg_] * D2H + ck + ch0 * 8);             \
        CP_ASYNC16(dst + 0 * TILEB + r1c * RSZ + ch1 * 16,                      \
                   flatHi + (size_t)ia1[sg_] * D2H + ck + ch1 * 8);             \
        CP_ASYNC16(dst + 1 * TILEB + r0c * RSZ + ch0 * 16,                      \
                   Bhi + (size_t)(n0 + r0c) * K + kb + ch0 * 8);                \
        CP_ASYNC16(dst + 1 * TILEB + r1c * RSZ + ch1 * 16,                      \
                   Bhi + (size_t)(n0 + r1c) * K + kb + ch1 * 8);                \
        CP_COMMIT();                                                            \
    } while (0)

    LOAD_STAGE_G(0);

    for (int c = 0; c < nch; ++c) {
        if (c + 1 < nch) { LOAD_STAGE_G(c + 1); CP_WAIT(1); }
        else             { CP_WAIT(0); }
        __syncthreads();

        const uint32_t s = sb + (c & 1) * STAGE2;
        const uint32_t aHiB = s, bHiB = s + TILEB;

        #pragma unroll
        for (int ks = 0; ks < 2; ++ks) {
            const uint32_t colOff = (uint32_t)(ks * 2 + cA) * 16;
            uint32_t aHi[4][4], bHi[4][2];
            #pragma unroll
            for (int mt = 0; mt < 4; ++mt) {
                uint32_t ad = (uint32_t)(wm * 64 + mt * 16 + rA) * RSZ + colOff;
                LDSM_X4(aHi[mt], aHiB + ad);
            }
            #pragma unroll
            for (int nh = 0; nh < 2; ++nh) {
                uint32_t bd = (uint32_t)(wn * 32 + nh * 16 + rA) * RSZ + colOff;
                uint32_t t[4];
                LDSM_X4(t, bHiB + bd);
                bHi[nh * 2 + 0][0] = t[0]; bHi[nh * 2 + 0][1] = t[2];
                bHi[nh * 2 + 1][0] = t[1]; bHi[nh * 2 + 1][1] = t[3];
            }
            #pragma unroll
            for (int mt = 0; mt < 4; ++mt)
                #pragma unroll
                for (int nt = 0; nt < 4; ++nt)
                    MMA_FP16(acc[mt][nt], aHi[mt], bHi[nt]);
        }
        __syncthreads();
    }

    // ---- epilogue: fmap + atomicMax scatter into segment keys ----
    const int rr = lane >> 2, cc2 = (lane & 3) * 2;
    #pragma unroll
    for (int mt = 0; mt < 4; ++mt) {
        int rowL = wm * 64 + mt * 16 + rr;
        int mA = m0 + rowL, mB = mA + 8;
        int sgA = (mA < MM) ? seg[mA] : -1;
        int sgB = (mB < MM) ? seg[mB] : -1;
        #pragma unroll
        for (int nt = 0; nt < 4; ++nt) {
            int col = n0 + wn * 32 + nt * 8 + cc2;
            if (sgA >= 0) {
                unsigned* d = keys + (size_t)sgA * D2H + col;
                atomicMax(d,     fmap(acc[mt][nt][0]));
                atomicMax(d + 1, fmap(acc[mt][nt][1]));
            }
            if (sgB >= 0) {
                unsigned* d = keys + (size_t)sgB * D2H + col;
                atomicMax(d,     fmap(acc[mt][nt][2]));
                atomicMax(d + 1, fmap(acc[mt][nt][3]));
            }
        }
    }
    #undef LOAD_STAGE_G
}

// ---------------------------------------------------------------------------
// Pack kernels
// ---------------------------------------------------------------------------
__global__ void convert_pad_kernel(const float* __restrict__ src,
                                   __half* __restrict__ hi,
                                   int rows, int sk, int dk) {
    size_t total = (size_t)rows * dk;
    for (size_t idx = blockIdx.x * (size_t)blockDim.x + threadIdx.x; idx < total;
         idx += (size_t)gridDim.x * blockDim.x) {
        int r = (int)(idx / dk), c = (int)(idx % dk);
        float f = (c < sk) ? src[(size_t)r * sk + c] : 0.0f;
        hi[idx] = __float2half(f);
    }
}

// wih: src row g*256+j -> dst row j*4+g (within its direction half), pad to EP
__global__ void pack_wih_kernel(const float* __restrict__ wih,
                                const float* __restrict__ b,
                                __half* __restrict__ hi,
                                float* __restrict__ pb) {
    const int total = G4 * EP;
    for (int idx = blockIdx.x * blockDim.x + threadIdx.x; idx < total;
         idx += gridDim.x * blockDim.x) {
        int rp = idx / EP, k = idx % EP;
        int j = rp >> 2, g = rp & 3;
        float f = (k < EE) ? wih[(size_t)(g * 256 + j) * EE + k] : 0.0f;
        hi[idx] = __float2half(f);
        if (k == 0) pb[rp] = b[g * 256 + j];
    }
}

__global__ void pack_whh_kernel(const float* __restrict__ whh,
                                __half* __restrict__ hi,
                                __half* __restrict__ lo) {
    const int total = G4 * HH;
    for (int idx = blockIdx.x * blockDim.x + threadIdx.x; idx < total;
         idx += gridDim.x * blockDim.x) {
        int rp = idx >> 8, k = idx & 255;
        int j = rp >> 2, g = rp & 3;
        float v = whh[(size_t)(g * 256 + j) * HH + k];
        __half h, l; splith(v, h, l);
        hi[idx] = h; lo[idx] = l;
    }
}

__global__ void pack_pairWT_kernel(const float* __restrict__ pair_hW,
                                   __half* __restrict__ hi) {
    const int total = 3 * D2H * G4;
    for (int idx = blockIdx.x * blockDim.x + threadIdx.x; idx < total;
         idx += gridDim.x * blockDim.x) {
        int k = idx / (D2H * G4);
        int rem = idx - k * (D2H * G4);
        int n = rem >> 10, kk = rem & 1023;
        hi[idx] = __float2half(pair_hW[(size_t)k * (G4 * D2H) + (size_t)kk * D2H + n]);
    }
}

__global__ void pack_triWT_kernel(const float* __restrict__ tri_hW,
                                  __half* __restrict__ hi) {
    const int total = D2H * 1536;
    for (int idx = blockIdx.x * blockDim.x + threadIdx.x; idx < total;
         idx += gridDim.x * blockDim.x) {
        int n = idx / 1536, kk = idx % 1536;
        hi[idx] = __float2half(tri_hW[(size_t)kk * D2H + n]);
    }
}

__global__ void pack_allWT_kernel(const float* __restrict__ all_hW,
                                  __half* __restrict__ hi) {
    const int total = D2H * 2048;
    for (int idx = blockIdx.x * blockDim.x + threadIdx.x; idx < total;
         idx += gridDim.x * blockDim.x) {
        int n = idx >> 11, k = idx & 2047;
        hi[idx] = __float2half(all_hW[(size_t)k * D2H + n]);
    }
}

__global__ void zero_keys_kernel(unsigned* __restrict__ pk, unsigned* __restrict__ tk) {
    const size_t np = (size_t)3 * CC * D2H;
    const size_t nt = (size_t)CC * D2H;
    for (size_t i = blockIdx.x * (size_t)blockDim.x + threadIdx.x; i < np + nt;
         i += (size_t)gridDim.x * blockDim.x) {
        if (i < np) pk[i] = 0u; else tk[i - np] = 0u;
    }
}

// ---------------------------------------------------------------------------
// Persistent HMMA BiLSTM recurrence (fp16 3-term; 8-CTA group barriers,
// fp32 Gx (combined F|B layout, row stride 2048) prefetched at step start).
// ---------------------------------------------------------------------------
#define PRSZ   528
#define LP_AHI 0
#define LP_ALO 16896
#define LP_BHI 33792
#define LP_BLO 101376
#define SMEM_LSTMP 168960

__global__ __launch_bounds__(256, 1)
void lstm_persist_kernel(const float* __restrict__ Gx,
                         const __half* __restrict__ whhHiF,
                         const __half* __restrict__ whhLoF,
                         const __half* __restrict__ whhHiB,
                         const __half* __restrict__ whhLoB,
                         __half* __restrict__ flatHi,
                         __half* __restrict__ flatLo) {
    extern __shared__ char smem[];
    const uint32_t sb = smem_u32(smem);
    const int tid = threadIdx.x, lane = tid & 31, wid = tid >> 5;
    const int dir = blockIdx.z;
    const int p0 = blockIdx.x * 32;
    const int c0 = blockIdx.y * 128;
    const int hcol = dir * HH;
    const int gcol = dir * G4;      // column offset into combined Gx
    const int bidx = dir * 8 + blockIdx.x;
    const __half* Whi = dir ? whhHiB : whhHiF;
    const __half* Wlo = dir ? whhLoB : whhLoF;

    for (int ch = tid; ch < 128 * 32; ch += 256) {
        int row = ch >> 5, cb = ch & 31;
        size_t src = (size_t)(c0 + row) * HH + cb * 8;
        CP_ASYNC16(sb + LP_BHI + row * PRSZ + cb * 16, Whi + src);
        CP_ASYNC16(sb + LP_BLO + row * PRSZ + cb * 16, Wlo + src);
    }
    CP_COMMIT(); CP_WAIT(0);
    __syncthreads();

    float creg[2][2] = {{0.f, 0.f}, {0.f, 0.f}};
    const int rr = lane >> 2, cc2 = (lane & 3) * 2;
    const bool evenT = ((lane & 1) == 0);

    for (int s = 0; s < TT; ++s) {
        const int tcur = dir ? (TT - 1 - s) : s;

        // ---- prefetch Gx for this step (fp32, combined layout)
        float2 gpre[2][2][2];
        #pragma unroll
        for (int mt = 0; mt < 2; ++mt) {
            #pragma unroll
            for (int nt = 0; nt < 2; ++nt) {
                int prow = p0 + mt * 16 + rr;
                int col = gcol + c0 + wid * 16 + nt * 8 + cc2;
                size_t n0i = (size_t)tcur * PP + prow;
                gpre[mt][nt][0] = *(const float2*)&Gx[n0i * G8 + col];
                gpre[mt][nt][1] = *(const float2*)&Gx[(n0i + 8) * G8 + col];
            }
        }

        float acc[2][2][4];
        #pragma unroll
        for (int i = 0; i < 2; ++i)
            #pragma unroll
            for (int j = 0; j < 2; ++j)
                #pragma unroll
                for (int q = 0; q < 4; ++q) acc[i][j][q] = 0.0f;

        if (s > 0) {
            group_barrier(bidx, tid, 8u);

            const int nprev = dir ? (tcur + 1) : (tcur - 1);
            for (int ch = tid; ch < 32 * 32; ch += 256) {
                int row = ch >> 5, cb = ch & 31;
                size_t src = (size_t)(nprev * PP + p0 + row) * D2H + hcol + cb * 8;
                CP_ASYNC16(sb + LP_AHI + row * PRSZ + cb * 16, flatHi + src);
                CP_ASYNC16(sb + LP_ALO + row * PRSZ + cb * 16, flatLo + src);
            }
            CP_COMMIT(); CP_WAIT(0);
            __syncthreads();

            #pragma unroll 4
            for (int kc = 0; kc < 16; ++kc) {
                const uint32_t colOff = (uint32_t)kc * 32 + (uint32_t)(lane >> 4) * 16;
                uint32_t aHi[2][4], bHi[2][2];
                #pragma unroll
                for (int mt = 0; mt < 2; ++mt) {
                    uint32_t ad = (uint32_t)(mt * 16 + (lane & 15)) * PRSZ + colOff;
                    LDSM_X4(aHi[mt], sb + LP_AHI + ad);
                }
                {
                    uint32_t bd = (uint32_t)(wid * 16 + (lane & 15)) * PRSZ + colOff;
                    uint32_t t[4];
                    LDSM_X4(t, sb + LP_BHI + bd);
                    bHi[0][0] = t[0]; bHi[0][1] = t[2];
                    bHi[1][0] = t[1]; bHi[1][1] = t[3];
                }
                #pragma unroll
                for (int mt = 0; mt < 2; ++mt)
                    #pragma unroll
                    for (int nt = 0; nt < 2; ++nt)
                        MMA_FP16(acc[mt][nt], aHi[mt], bHi[nt]);
                {
                    uint32_t aLo[2][4];
                    #pragma unroll
                    for (int mt = 0; mt < 2; ++mt) {
                        uint32_t ad = (uint32_t)(mt * 16 + (lane & 15)) * PRSZ + colOff;
                        LDSM_X4(aLo[mt], sb + LP_ALO + ad);
                    }
                    #pragma unroll
                    for (int mt = 0; mt < 2; ++mt)
                        #pragma unroll
                        for (int nt = 0; nt < 2; ++nt)
                            MMA_FP16(acc[mt][nt], aLo[mt], bHi[nt]);
                }
                {
                    uint32_t bLo[2][2];
                    uint32_t bd = (uint32_t)(wid * 16 + (lane & 15)) * PRSZ + colOff;
                    uint32_t t[4];
                    LDSM_X4(t, sb + LP_BLO + bd);
                    bLo[0][0] = t[0]; bLo[0][1] = t[2];
                    bLo[1][0] = t[1]; bLo[1][1] = t[3];
                    #pragma unroll
                    for (int mt = 0; mt < 2; ++mt)
                        #pragma unroll
                        for (int nt = 0; nt < 2; ++nt)
                            MMA_FP16(acc[mt][nt], aHi[mt], bLo[nt]);
                }
            }
        }

        #pragma unroll
        for (int mt = 0; mt < 2; ++mt) {
            #pragma unroll
            for (int nt = 0; nt < 2; ++nt) {
                int prow = p0 + mt * 16 + rr;
                int col = c0 + wid * 16 + nt * 8 + cc2;
                int j = col >> 2;
                float2 g0 = gpre[mt][nt][0];
                float2 g1 = gpre[mt][nt][1];
                float v0 = acc[mt][nt][0] + g0.x;
                float v1 = acc[mt][nt][1] + g0.y;
                float v2 = acc[mt][nt][2] + g1.x;
                float v3 = acc[mt][nt][3] + g1.y;
                float w0 = __shfl_xor_sync(0xffffffffu, v0, 1);
                float w1 = __shfl_xor_sync(0xffffffffu, v1, 1);
                float w2 = __shfl_xor_sync(0xffffffffu, v2, 1);
                float w3 = __shfl_xor_sync(0xffffffffu, v3, 1);
                float I, F, G, O;
                int p;
                if (evenT) { I = v0; F = v1; G = w0; O = w1; p = prow; }
                else       { I = w2; F = w3; G = v2; O = v3; p = prow + 8; }
                float cold = creg[mt][nt];
                float cn = sigmoidf_(F) * cold + sigmoidf_(I) * tanhf(G);
                float h = sigmoidf_(O) * tanhf(cn);
                creg[mt][nt] = cn;
                size_t nn = (size_t)tcur * PP + p;
                __half hh, hl; splith(h, hh, hl);
                flatHi[nn * D2H + hcol + j] = hh;
                flatLo[nn * D2H + hcol + j] = hl;
            }
        }
        __syncthreads();
    }
}

// ---------------------------------------------------------------------------
// Finalize kernels
// ---------------------------------------------------------------------------
__global__ __launch_bounds__(256)
void pair_final_kernel(const unsigned* __restrict__ keys,
                       const float* __restrict__ hb,
                       const float* __restrict__ backoff,
                       const float* __restrict__ oW,
                       const float* __restrict__ ob,
                       float* __restrict__ pv, float* __restrict__ out) {
    const int b = blockIdx.x;
    const int k = b >> 14;
    const unsigned* src = keys + (size_t)b * D2H;
    float partial = 0.0f;
    #pragma unroll
    for (int it = 0; it < 2; ++it) {
        int c = threadIdx.x + it * 256;
        unsigned u = src[c];
        float val = u ? (funmap(u) + hb[k * D2H + c]) : backoff[k * D2H + c];
        float t = tanhf(val);
        pv[(size_t)b * D2H + c] = t;
        partial += t * oW[k * D2H + c];
    }
    float tot = blockReduceSum256(partial);
    if (threadIdx.x == 0) out[CC + b] = tot + ob[k];
}

__global__ __launch_bounds__(256)
void tri_final_kernel(const unsigned* __restrict__ keys,
                      const float* __restrict__ hb,
                      const float* __restrict__ backoff,
                      float* __restrict__ tv) {
    const int s = blockIdx.x;
    const unsigned* src = keys + (size_t)s * D2H;
    #pragma unroll
    for (int it = 0; it < 2; ++it) {
        int c = threadIdx.x + it * 256;
        unsigned u = src[c];
        float val = u ? (funmap(u) + hb[c]) : backoff[c];
        tv[(size_t)s * D2H + c] = tanhf(val);
    }
}

// gather 8H features (fp16 hi only)
__global__ void gather_feats_kernel(const float* __restrict__ pv,
                                    const float* __restrict__ tv,
                                    const int* __restrict__ tpi,
                                    __half* __restrict__ fhi) {
    const int s = blockIdx.x;
    const int i0 = tpi[s * 3 + 0];
    const int i1 = tpi[s * 3 + 1];
    const int i2 = tpi[s * 3 + 2];
    for (int j = threadIdx.x; j < 2048; j += blockDim.x) {
        int q = j >> 9, c = j & 511;
        float v;
        if (q == 0)      v = pv[((size_t)2 * CC + i0) * D2H + c];
        else if (q == 1) v = pv[((size_t)1 * CC + i1) * D2H + c];
        else if (q == 2) v = pv[(size_t)i2 * D2H + c];
        else             v = tv[(size_t)s * D2H + c];
        fhi[(size_t)s * 2048 + j] = __float2half(v);
    }
}

__global__ __launch_bounds__(256)
void triple_logit_kernel(const float* __restrict__ fin,
                         const float* __restrict__ tW,
                         const float* __restrict__ tb,
                         float* __restrict__ out) {
    const int s = blockIdx.x;
    float partial = 0.0f;
    #pragma unroll
    for (int it = 0; it < 2; ++it) {
        int c = threadIdx.x + it * 256;
        float v = fin[(size_t)s * D2H + c];
        v = v > 0.0f ? v : 0.0f;
        partial += v * tW[c];
    }
    float tot = blockReduceSum256(partial);
    if (threadIdx.x == 0) out[s] = tot + tb[0];
}

// ---------------------------------------------------------------------------
// Launcher
// ---------------------------------------------------------------------------
extern "C" void kernel_launch(void* const* d_in, const int* in_sizes, int n_in,
                              void* d_out, int out_size) {
    const float* x        = (const float*)d_in[0];
    const float* wih_f    = (const float*)d_in[1];
    const float* whh_f    = (const float*)d_in[2];
    const float* b_f      = (const float*)d_in[3];
    const float* wih_b    = (const float*)d_in[4];
    const float* whh_b    = (const float*)d_in[5];
    const float* b_b      = (const float*)d_in[6];
    const float* pair_hW  = (const float*)d_in[7];
    const float* pair_hb  = (const float*)d_in[8];
    const float* pair_oW  = (const float*)d_in[9];
    const float* pair_ob  = (const float*)d_in[10];
    const float* pair_bo  = (const float*)d_in[11];
    const float* tri_hW   = (const float*)d_in[12];
    const float* tri_hb   = (const float*)d_in[13];
    const float* tri_bo   = (const float*)d_in[14];
    const float* all_hW   = (const float*)d_in[15];
    const float* all_hb   = (const float*)d_in[16];
    const float* out_tW   = (const float*)d_in[17];
    const float* out_tb   = (const float*)d_in[18];
    const int*   occ1     = (const int*)d_in[19];
    const int*   occ2     = (const int*)d_in[20];
    const int*   seg      = (const int*)d_in[21];
    const int*   tri_o1   = (const int*)d_in[22];
    const int*   tri_o2   = (const int*)d_in[23];
    const int*   tri_o3   = (const int*)d_in[24];
    const int*   tri_seg  = (const int*)d_in[25];
    const int*   tri_pi   = (const int*)d_in[26];
    float* out = (float*)d_out;

    float *Gx, *pv, *tv, *fin, *pb;
    unsigned *pk, *tk;
    __half *xHi, *wHi, *flHi, *flLo;
    __half *whF, *wlF, *whB, *wlB;
    __half *pwHi, *twHi, *awHi, *ftHi;
    cudaGetSymbolAddress((void**)&Gx,   g_Gx);
    cudaGetSymbolAddress((void**)&pk,   g_pairKeys);
    cudaGetSymbolAddress((void**)&tk,   g_triKeys);
    cudaGetSymbolAddress((void**)&pv,   g_pv);
    cudaGetSymbolAddress((void**)&tv,   g_tv);
    cudaGetSymbolAddress((void**)&fin,  g_final);
    cudaGetSymbolAddress((void**)&pb,   g_pb);
    cudaGetSymbolAddress((void**)&xHi,  g_xHi);
    cudaGetSymbolAddress((void**)&wHi,  g_wHi);
    cudaGetSymbolAddress((void**)&whF,  g_whhHiF);
    cudaGetSymbolAddress((void**)&wlF,  g_whhLoF);
    cudaGetSymbolAddress((void**)&whB,  g_whhHiB);
    cudaGetSymbolAddress((void**)&wlB,  g_whhLoB);
    cudaGetSymbolAddress((void**)&flHi, g_flatHi);
    cudaGetSymbolAddress((void**)&flLo, g_flatLo);
    cudaGetSymbolAddress((void**)&pwHi, g_pwHi);
    cudaGetSymbolAddress((void**)&twHi, g_twHi);
    cudaGetSymbolAddress((void**)&awHi, g_aWHi);
    cudaGetSymbolAddress((void**)&ftHi, g_ftHi);

    cudaFuncSetAttribute(gemm_fp16x1_kernel,
                         cudaFuncAttributeMaxDynamicSharedMemorySize, SMEM_G1);
    cudaFuncSetAttribute(gemm_gsc_kernel,
                         cudaFuncAttributeMaxDynamicSharedMemorySize, SMEM_G1);
    cudaFuncSetAttribute(lstm_persist_kernel,
                         cudaFuncAttributeMaxDynamicSharedMemorySize, SMEM_LSTMP);

    // 1) convert/pack operands (fp16); wih F into rows 0..1023, B into 1024..2047
    convert_pad_kernel<<<4096, 256>>>(x, xHi, NPOS, EE, EP);
    pack_wih_kernel<<<512, 256>>>(wih_f, b_f, wHi, pb);
    pack_wih_kernel<<<512, 256>>>(wih_b, b_b, wHi + (size_t)G4 * EP, pb + G4);
    pack_whh_kernel<<<512, 256>>>(whh_f, whF, wlF);
    pack_whh_kernel<<<512, 256>>>(whh_b, whB, wlB);
    pack_pairWT_kernel<<<3072, 256>>>(pair_hW, pwHi);
    pack_triWT_kernel<<<1536, 256>>>(tri_hW, twHi);
    pack_allWT_kernel<<<1024, 256>>>(all_hW, awHi);

    // 2) fused input projection (both dirs): Gx = xHi @ [wihF|wihB]^T + pb
    gemm_fp16x1_kernel<<<dim3(16, 512), 256, SMEM_G1>>>(xHi, wHi, pb, Gx, EP);

    // 3) zero segment-max keys
    zero_keys_kernel<<<32768, 256>>>(pk, tk);

    // 4) BiLSTM recurrence: persistent HMMA kernel (fp16 3-term)
    lstm_persist_kernel<<<dim3(8, 8, 2), 256, SMEM_LSTMP>>>(
        Gx, whF, wlF, whB, wlB, flHi, flLo);

    // 5) gather-GEMM-scatter: pair types + triples (fp16 1-term)
    for (int k = 0; k < 3; ++k)
        gemm_gsc_kernel<<<dim3(4, MTILES), 256, SMEM_G1>>>(
            flHi, pwHi + (size_t)k * D2H * G4,
            occ1 + k * MM, occ2 + k * MM, occ1 + k * MM,
            seg + k * MM, pk + (size_t)k * CC * D2H, G4);
    gemm_gsc_kernel<<<dim3(4, MTILES), 256, SMEM_G1>>>(
        flHi, twHi, tri_o1, tri_o2, tri_o3, tri_seg, tk, 1536);

    // 6) finalize pooled vectors (+ pair logits)
    pair_final_kernel<<<3 * CC, 256>>>(pk, pair_hb, pair_bo, pair_oW, pair_ob, pv, out);
    tri_final_kernel<<<CC, 256>>>(tk, tri_hb, tri_bo, tv);

    // 7) final MLP + triple logits (fp16 1-term, contiguous ftHi)
    gather_feats_kernel<<<CC, 256>>>(pv, tv, tri_pi, ftHi);
    gemm_fp16x1_kernel<<<dim3(D2H / 128, CC / 128), 256, SMEM_G1>>>(
        ftHi, awHi, all_hb, fin, 2048);
    triple_logit_kernel<<<CC, 256>>>(fin, out_tW, out_tb, out);
}

// round 16
// speedup vs baseline: 1.0530x; 1.0193x over previous
#include <cuda_runtime.h>
#include <cuda_fp16.h>
#include <math.h>
#include <stdint.h>

// ---------------------------------------------------------------------------
// Problem constants
// ---------------------------------------------------------------------------
#define TT   256
#define PP   256
#define EE   300
#define HH   256
#define NPOS 65536            // T*P
#define G4   1024             // 4H
#define G8   2048             // both directions
#define D2H  512              // 2H
#define MM   50000
#define CC   16384
#define EP   320              // E padded to multiple of 32
#define MTILES ((MM + 127) / 128)   // 391

// ---------------------------------------------------------------------------
// Device scratch (static allocations only)
// ---------------------------------------------------------------------------
__device__ float    g_Gx[(size_t)NPOS * G8];           // 536 MB fp32, F|B halves
__device__ unsigned g_pairKeys[(size_t)3 * CC * D2H];  // 100 MB
__device__ unsigned g_triKeys[(size_t)CC * D2H];       // 33 MB
__device__ float    g_pv[(size_t)3 * CC * D2H];        // 100 MB
__device__ float    g_tv[(size_t)CC * D2H];            // 33 MB
__device__ float    g_final[(size_t)CC * D2H];         // 33 MB
__device__ float    g_pb[G8];                          // permuted biases F|B
__device__ unsigned g_barCnt[16];                      // per (dir,ptile) barrier
__device__ unsigned g_barGen[16];

// fp16 operand buffers
__device__ __half g_xHi[(size_t)NPOS * EP];            // 42 MB (hi only)
__device__ __half g_wHi[(size_t)G8 * EP];              // packed rows (dir,j*4+g)
__device__ __half g_whhHiF[(size_t)G4 * HH];           // packed rows j*4+g
__device__ __half g_whhLoF[(size_t)G4 * HH];
__device__ __half g_whhHiB[(size_t)G4 * HH];
__device__ __half g_whhLoB[(size_t)G4 * HH];
__device__ __half g_flatHi[(size_t)NPOS * D2H];        // 67 MB
__device__ __half g_flatLo[(size_t)NPOS * D2H];        // used by LSTM only
__device__ __half g_pwHi[(size_t)3 * D2H * G4];        // pairWT [3][512][1024]
__device__ __half g_twHi[(size_t)D2H * 1536];          // triWT [512][1536]
__device__ __half g_aWHi[(size_t)D2H * 2048];
__device__ __half g_ftHi[(size_t)CC * 2048];           // 67 MB (hi only)

// ---------------------------------------------------------------------------
// Helpers
// ---------------------------------------------------------------------------
__device__ __forceinline__ uint32_t smem_u32(const void* p) {
    uint32_t a;
    asm("{ .reg .u64 t; cvta.to.shared.u64 t, %1; cvt.u32.u64 %0, t; }"
        : "=r"(a) : "l"(p));
    return a;
}

#define LDSM_X4(r, addr) \
    asm volatile("ldmatrix.sync.aligned.m8n8.x4.shared.b16 {%0,%1,%2,%3}, [%4];" \
        : "=r"((r)[0]), "=r"((r)[1]), "=r"((r)[2]), "=r"((r)[3]) : "r"(addr))

#define MMA_FP16(d, a, b) \
    asm volatile("mma.sync.aligned.m16n8k16.row.col.f32.f16.f16.f32 " \
        "{%0,%1,%2,%3}, {%4,%5,%6,%7}, {%8,%9}, {%0,%1,%2,%3};" \
        : "+f"((d)[0]), "+f"((d)[1]), "+f"((d)[2]), "+f"((d)[3]) \
        : "r"((a)[0]), "r"((a)[1]), "r"((a)[2]), "r"((a)[3]), \
          "r"((b)[0]), "r"((b)[1]))

#define CP_ASYNC16(dst, src) \
    asm volatile("cp.async.cg.shared.global [%0], [%1], 16;" \
                 :: "r"(dst), "l"(src))
#define CP_COMMIT() asm volatile("cp.async.commit_group;" ::: "memory")
#define CP_WAIT(n)  asm volatile("cp.async.wait_group %0;" :: "n"(n) : "memory")

__device__ __forceinline__ float sigmoidf_(float x) { return 1.0f / (1.0f + expf(-x)); }

__device__ __forceinline__ unsigned fmap(float f) {
    unsigned b = __float_as_uint(f);
    return (b & 0x80000000u) ? ~b : (b | 0x80000000u);
}
__device__ __forceinline__ float funmap(unsigned u) {
    return (u & 0x80000000u) ? __uint_as_float(u & 0x7FFFFFFFu)
                             : __uint_as_float(~u);
}
__device__ __forceinline__ float warpReduceSum(float v) {
    #pragma unroll
    for (int o = 16; o > 0; o >>= 1) v += __shfl_down_sync(0xffffffffu, v, o);
    return v;
}
__device__ __forceinline__ float blockReduceSum256(float v) {
    __shared__ float sh[8];
    int lane = threadIdx.x & 31, wid = threadIdx.x >> 5;
    v = warpReduceSum(v);
    if (lane == 0) sh[wid] = v;
    __syncthreads();
    v = (threadIdx.x < 8) ? sh[threadIdx.x] : 0.0f;
    if (wid == 0) v = warpReduceSum(v);
    return v;
}
__device__ __forceinline__ void splith(float f, __half& h, __half& l) {
    h = __float2half(f);
    l = __float2half(f - __half2float(h));
}

// per-(dir,ptile) group barrier
__device__ __forceinline__ void group_barrier(int bidx, int tid, unsigned nCTA) {
    __syncthreads();
    if (tid == 0) {
        __threadfence();
        unsigned gen = atomicAdd(&g_barGen[bidx], 0u);
        unsigned prev = atomicAdd(&g_barCnt[bidx], 1u);
        if (prev == nCTA - 1u) {
            atomicExch(&g_barCnt[bidx], 0u);
            __threadfence();
            atomicAdd(&g_barGen[bidx], 1u);
        } else {
            while (atomicAdd(&g_barGen[bidx], 0u) == gen) { __nanosleep(32); }
        }
        __threadfence();
    }
    __syncthreads();
}

// ---------------------------------------------------------------------------
// Shared GEMM tile constants
// ---------------------------------------------------------------------------
#define RSZ   80
#define TILEB (128 * RSZ)       // 10240
#define STAGE2 (2 * TILEB)      // 20480 (Ahi, Bhi)
#define SMEM_G1 (2 * STAGE2)    // 40960

// ---------------------------------------------------------------------------
// fp16 1-term GEMM, fp32 output: C[M,N] = Ahi @ Bhi^T + bias
// CTA tile 128x128, 256 threads (8 warps: 2 M x 4 N; warp tile 64x32).
// ---------------------------------------------------------------------------
__global__ __launch_bounds__(256, 2)
void gemm_fp16x1_kernel(const __half* __restrict__ Ahi,
                        const __half* __restrict__ Bhi,
                        const float* __restrict__ bias,
                        float* __restrict__ C, int K) {
    extern __shared__ char smem[];
    const uint32_t sb = smem_u32(smem);
    const int tid = threadIdx.x, lane = tid & 31, wid = tid >> 5;
    const int m0 = blockIdx.y * 128, n0 = blockIdx.x * 128;
    const int ldc = gridDim.x * 128;
    const int wm = wid & 1, wn = wid >> 1;

    float acc[4][4][4];
    #pragma unroll
    for (int i = 0; i < 4; ++i)
        #pragma unroll
        for (int j = 0; j < 4; ++j)
            #pragma unroll
            for (int q = 0; q < 4; ++q) acc[i][j][q] = 0.0f;

    const int nch = K >> 5;
    const int r0c = (2 * tid) >> 2, ch0 = (2 * tid) & 3;
    const int r1c = (2 * tid + 1) >> 2, ch1 = (2 * tid + 1) & 3;
    const int rA = lane & 15;
    const int cA = lane >> 4;

    #define LOAD_STAGE(cc)                                                      \
    do {                                                                        \
        const int kb = (cc) << 5;                                               \
        const uint32_t dst = sb + ((cc) & 1) * STAGE2;                          \
        CP_ASYNC16(dst + 0 * TILEB + r0c * RSZ + ch0 * 16,                      \
                   Ahi + (size_t)(m0 + r0c) * K + kb + ch0 * 8);                \
        CP_ASYNC16(dst + 0 * TILEB + r1c * RSZ + ch1 * 16,                      \
                   Ahi + (size_t)(m0 + r1c) * K + kb + ch1 * 8);                \
        CP_ASYNC16(dst + 1 * TILEB + r0c * RSZ + ch0 * 16,                      \
                   Bhi + (size_t)(n0 + r0c) * K + kb + ch0 * 8);                \
        CP_ASYNC16(dst + 1 * TILEB + r1c * RSZ + ch1 * 16,                      \
                   Bhi + (size_t)(n0 + r1c) * K + kb + ch1 * 8);                \
        CP_COMMIT();                                                            \
    } while (0)

    LOAD_STAGE(0);

    for (int c = 0; c < nch; ++c) {
        if (c + 1 < nch) { LOAD_STAGE(c + 1); CP_WAIT(1); }
        else             { CP_WAIT(0); }
        __syncthreads();

        const uint32_t s = sb + (c & 1) * STAGE2;
        const uint32_t aHiB = s, bHiB = s + TILEB;

        #pragma unroll
        for (int ks = 0; ks < 2; ++ks) {
            const uint32_t colOff = (uint32_t)(ks * 2 + cA) * 16;
            uint32_t aHi[4][4], bHi[4][2];
            #pragma unroll
            for (int mt = 0; mt < 4; ++mt) {
                uint32_t ad = (uint32_t)(wm * 64 + mt * 16 + rA) * RSZ + colOff;
                LDSM_X4(aHi[mt], aHiB + ad);
            }
            #pragma unroll
            for (int nh = 0; nh < 2; ++nh) {
                uint32_t bd = (uint32_t)(wn * 32 + nh * 16 + rA) * RSZ + colOff;
                uint32_t t[4];
                LDSM_X4(t, bHiB + bd);
                bHi[nh * 2 + 0][0] = t[0]; bHi[nh * 2 + 0][1] = t[2];
                bHi[nh * 2 + 1][0] = t[1]; bHi[nh * 2 + 1][1] = t[3];
            }
            #pragma unroll
            for (int mt = 0; mt < 4; ++mt)
                #pragma unroll
                for (int nt = 0; nt < 4; ++nt)
                    MMA_FP16(acc[mt][nt], aHi[mt], bHi[nt]);
        }
        __syncthreads();
    }

    const int rr = lane >> 2, cc2 = (lane & 3) * 2;
    #pragma unroll
    for (int mt = 0; mt < 4; ++mt) {
        #pragma unroll
        for (int nt = 0; nt < 4; ++nt) {
            int row = m0 + wm * 64 + mt * 16 + rr;
            int col = n0 + wn * 32 + nt * 8 + cc2;
            float b0 = 0.f, b1 = 0.f;
            if (bias) { b0 = bias[col]; b1 = bias[col + 1]; }
            float2 v0 = make_float2(acc[mt][nt][0] + b0, acc[mt][nt][1] + b1);
            float2 v1 = make_float2(acc[mt][nt][2] + b0, acc[mt][nt][3] + b1);
            *(float2*)&C[(size_t)row * ldc + col] = v0;
            *(float2*)&C[(size_t)(row + 8) * ldc + col] = v1;
        }
    }
    #undef LOAD_STAGE
}

// ---------------------------------------------------------------------------
// Combined gather-GEMM-scatter over all 4 occurrence types (blockIdx.z):
//   z in 0..2: pair type z, K=1024; z=3: triples, K=1536.
// rep[m] = concat(flatHi[occ..]) @ Bhi^T, then atomicMax into keys[seg[m]].
// ---------------------------------------------------------------------------
__global__ __launch_bounds__(256, 2)
void gemm_gsc_all_kernel(const __half* __restrict__ flatHi,
                         const __half* __restrict__ pwHi,
                         const __half* __restrict__ twHi,
                         const int* __restrict__ occ1,
                         const int* __restrict__ occ2,
                         const int* __restrict__ to1,
                         const int* __restrict__ to2,
                         const int* __restrict__ to3,
                         const int* __restrict__ pseg,
                         const int* __restrict__ tseg,
                         unsigned* __restrict__ pkeys,
                         unsigned* __restrict__ tkeys) {
    extern __shared__ char smem[];
    const uint32_t sb = smem_u32(smem);
    const int tid = threadIdx.x, lane = tid & 31, wid = tid >> 5;
    const int m0 = blockIdx.y * 128, n0 = blockIdx.x * 128;
    const int wm = wid & 1, wn = wid >> 1;
    const int z = blockIdx.z;

    const __half* Bhi;
    const int *o1, *o2, *o3, *sg;
    unsigned* keys;
    int K;
    if (z < 3) {
        Bhi = pwHi + (size_t)z * D2H * G4;
        o1 = occ1 + z * MM; o2 = occ2 + z * MM; o3 = o1;
        sg = pseg + z * MM;
        keys = pkeys + (size_t)z * CC * D2H;
        K = G4;
    } else {
        Bhi = twHi;
        o1 = to1; o2 = to2; o3 = to3;
        sg = tseg;
        keys = tkeys;
        K = 1536;
    }

    float acc[4][4][4];
    #pragma unroll
    for (int i = 0; i < 4; ++i)
        #pragma unroll
        for (int j = 0; j < 4; ++j)
            #pragma unroll
            for (int q = 0; q < 4; ++q) acc[i][j][q] = 0.0f;

    const int nch = K >> 5;
    const int r0c = (2 * tid) >> 2, ch0 = (2 * tid) & 3;
    const int r1c = (2 * tid + 1) >> 2, ch1 = (2 * tid + 1) & 3;
    const int rA = lane & 15;
    const int cA = lane >> 4;

    const int mC0 = (m0 + r0c < MM) ? (m0 + r0c) : (MM - 1);
    const int mC1 = (m0 + r1c < MM) ? (m0 + r1c) : (MM - 1);
    int ia0[3], ia1[3];
    ia0[0] = o1[mC0]; ia1[0] = o1[mC1];
    ia0[1] = o2[mC0]; ia1[1] = o2[mC1];
    ia0[2] = (K > 1024) ? o3[mC0] : 0;
    ia1[2] = (K > 1024) ? o3[mC1] : 0;

    #define LOAD_STAGE_G(cc)                                                    \
    do {                                                                        \
        const int kb = (cc) << 5;                                               \
        const int sg_ = kb >> 9;                                                \
        const int ck = kb & 511;                                                \
        const uint32_t dst = sb + ((cc) & 1) * STAGE2;                          \
        CP_ASYNC16(dst + 0 * TILEB + r0c * RSZ + ch0 * 16,                      \
                   flatHi + (size_t)ia0[sg_] * D2H + ck + ch0 * 8);             \
        CP_ASYNC16(dst + 0 * TILEB + r1c * RSZ + ch1 * 16,                      \
                   flatHi + (size_t)ia1[sg_] * D2H + ck + ch1 * 8);             \
        CP_ASYNC16(dst + 1 * TILEB + r0c * RSZ + ch0 * 16,                      \
                   Bhi + (size_t)(n0 + r0c) * K + kb + ch0 * 8);                \
        CP_ASYNC16(dst + 1 * TILEB + r1c * RSZ + ch1 * 16,                      \
                   Bhi + (size_t)(n0 + r1c) * K + kb + ch1 * 8);                \
        CP_COMMIT();                                                            \
    } while (0)

    LOAD_STAGE_G(0);

    for (int c = 0; c < nch; ++c) {
        if (c + 1 < nch) { LOAD_STAGE_G(c + 1); CP_WAIT(1); }
        else             { CP_WAIT(0); }
        __syncthreads();

        const uint32_t s = sb + (c & 1) * STAGE2;
        const uint32_t aHiB = s, bHiB = s + TILEB;

        #pragma unroll
        for (int ks = 0; ks < 2; ++ks) {
            const uint32_t colOff = (uint32_t)(ks * 2 + cA) * 16;
            uint32_t aHi[4][4], bHi[4][2];
            #pragma unroll
            for (int mt = 0; mt < 4; ++mt) {
                uint32_t ad = (uint32_t)(wm * 64 + mt * 16 + rA) * RSZ + colOff;
                LDSM_X4(aHi[mt], aHiB + ad);
            }
            #pragma unroll
            for (int nh = 0; nh < 2; ++nh) {
                uint32_t bd = (uint32_t)(wn * 32 + nh * 16 + rA) * RSZ + colOff;
                uint32_t t[4];
                LDSM_X4(t, bHiB + bd);
                bHi[nh * 2 + 0][0] = t[0]; bHi[nh * 2 + 0][1] = t[2];
                bHi[nh * 2 + 1][0] = t[1]; bHi[nh * 2 + 1][1] = t[3];
            }
            #pragma unroll
            for (int mt = 0; mt < 4; ++mt)
                #pragma unroll
                for (int nt = 0; nt < 4; ++nt)
                    MMA_FP16(acc[mt][nt], aHi[mt], bHi[nt]);
        }
        __syncthreads();
    }

    // ---- epilogue: fmap + atomicMax scatter into segment keys ----
    const int rr = lane >> 2, cc2 = (lane & 3) * 2;
    #pragma unroll
    for (int mt = 0; mt < 4; ++mt) {
        int rowL = wm * 64 + mt * 16 + rr;
        int mA = m0 + rowL, mB = mA + 8;
        int sgA = (mA < MM) ? sg[mA] : -1;
        int sgB = (mB < MM) ? sg[mB] : -1;
        #pragma unroll
        for (int nt = 0; nt < 4; ++nt) {
            int col = n0 + wn * 32 + nt * 8 + cc2;
            if (sgA >= 0) {
                unsigned* d = keys + (size_t)sgA * D2H + col;
                atomicMax(d,     fmap(acc[mt][nt][0]));
                atomicMax(d + 1, fmap(acc[mt][nt][1]));
            }
            if (sgB >= 0) {
                unsigned* d = keys + (size_t)sgB * D2H + col;
                atomicMax(d,     fmap(acc[mt][nt][2]));
                atomicMax(d + 1, fmap(acc[mt][nt][3]));
            }
        }
    }
    #undef LOAD_STAGE_G
}

// ---------------------------------------------------------------------------
// Pack kernels
// ---------------------------------------------------------------------------
__global__ void convert_pad_kernel(const float* __restrict__ src,
                                   __half* __restrict__ hi,
                                   int rows, int sk, int dk) {
    size_t total = (size_t)rows * dk;
    for (size_t idx = blockIdx.x * (size_t)blockDim.x + threadIdx.x; idx < total;
         idx += (size_t)gridDim.x * blockDim.x) {
        int r = (int)(idx / dk), c = (int)(idx % dk);
        float f = (c < sk) ? src[(size_t)r * sk + c] : 0.0f;
        hi[idx] = __float2half(f);
    }
}

__global__ void pack_wih_kernel(const float* __restrict__ wih,
                                const float* __restrict__ b,
                                __half* __restrict__ hi,
                                float* __restrict__ pb) {
    const int total = G4 * EP;
    for (int idx = blockIdx.x * blockDim.x + threadIdx.x; idx < total;
         idx += gridDim.x * blockDim.x) {
        int rp = idx / EP, k = idx % EP;
        int j = rp >> 2, g = rp & 3;
        float f = (k < EE) ? wih[(size_t)(g * 256 + j) * EE + k] : 0.0f;
        hi[idx] = __float2half(f);
        if (k == 0) pb[rp] = b[g * 256 + j];
    }
}

__global__ void pack_whh_kernel(const float* __restrict__ whh,
                                __half* __restrict__ hi,
                                __half* __restrict__ lo) {
    const int total = G4 * HH;
    for (int idx = blockIdx.x * blockDim.x + threadIdx.x; idx < total;
         idx += gridDim.x * blockDim.x) {
        int rp = idx >> 8, k = idx & 255;
        int j = rp >> 2, g = rp & 3;
        float v = whh[(size_t)(g * 256 + j) * HH + k];
        __half h, l; splith(v, h, l);
        hi[idx] = h; lo[idx] = l;
    }
}

__global__ void pack_pairWT_kernel(const float* __restrict__ pair_hW,
                                   __half* __restrict__ hi) {
    const int total = 3 * D2H * G4;
    for (int idx = blockIdx.x * blockDim.x + threadIdx.x; idx < total;
         idx += gridDim.x * blockDim.x) {
        int k = idx / (D2H * G4);
        int rem = idx - k * (D2H * G4);
        int n = rem >> 10, kk = rem & 1023;
        hi[idx] = __float2half(pair_hW[(size_t)k * (G4 * D2H) + (size_t)kk * D2H + n]);
    }
}

__global__ void pack_triWT_kernel(const float* __restrict__ tri_hW,
                                  __half* __restrict__ hi) {
    const int total = D2H * 1536;
    for (int idx = blockIdx.x * blockDim.x + threadIdx.x; idx < total;
         idx += gridDim.x * blockDim.x) {
        int n = idx / 1536, kk = idx % 1536;
        hi[idx] = __float2half(tri_hW[(size_t)kk * D2H + n]);
    }
}

__global__ void pack_allWT_kernel(const float* __restrict__ all_hW,
                                  __half* __restrict__ hi) {
    const int total = D2H * 2048;
    for (int idx = blockIdx.x * blockDim.x + threadIdx.x; idx < total;
         idx += gridDim.x * blockDim.x) {
        int n = idx >> 11, k = idx & 2047;
        hi[idx] = __float2half(all_hW[(size_t)k * D2H + n]);
    }
}

__global__ void zero_keys_kernel(unsigned* __restrict__ pk, unsigned* __restrict__ tk) {
    const size_t np = (size_t)3 * CC * D2H;
    const size_t nt = (size_t)CC * D2H;
    for (size_t i = blockIdx.x * (size_t)blockDim.x + threadIdx.x; i < np + nt;
         i += (size_t)gridDim.x * blockDim.x) {
        if (i < np) pk[i] = 0u; else tk[i - np] = 0u;
    }
}

// ---------------------------------------------------------------------------
// Persistent HMMA BiLSTM recurrence (fp16 3-term; 8-CTA group barriers,
// fp32 Gx (combined F|B layout, row stride 2048) prefetched at step start).
// ---------------------------------------------------------------------------
#define PRSZ   528
#define LP_AHI 0
#define LP_ALO 16896
#define LP_BHI 33792
#define LP_BLO 101376
#define SMEM_LSTMP 168960

__global__ __launch_bounds__(256, 1)
void lstm_persist_kernel(const float* __restrict__ Gx,
                         const __half* __restrict__ whhHiF,
                         const __half* __restrict__ whhLoF,
                         const __half* __restrict__ whhHiB,
                         const __half* __restrict__ whhLoB,
                         __half* __restrict__ flatHi,
                         __half* __restrict__ flatLo) {
    extern __shared__ char smem[];
    const uint32_t sb = smem_u32(smem);
    const int tid = threadIdx.x, lane = tid & 31, wid = tid >> 5;
    const int dir = blockIdx.z;
    const int p0 = blockIdx.x * 32;
    const int c0 = blockIdx.y * 128;
    const int hcol = dir * HH;
    const int gcol = dir * G4;
    const int bidx = dir * 8 + blockIdx.x;
    const __half* Whi = dir ? whhHiB : whhHiF;
    const __half* Wlo = dir ? whhLoB : whhLoF;

    for (int ch = tid; ch < 128 * 32; ch += 256) {
        int row = ch >> 5, cb = ch & 31;
        size_t src = (size_t)(c0 + row) * HH + cb * 8;
        CP_ASYNC16(sb + LP_BHI + row * PRSZ + cb * 16, Whi + src);
        CP_ASYNC16(sb + LP_BLO + row * PRSZ + cb * 16, Wlo + src);
    }
    CP_COMMIT(); CP_WAIT(0);
    __syncthreads();

    float creg[2][2] = {{0.f, 0.f}, {0.f, 0.f}};
    const int rr = lane >> 2, cc2 = (lane & 3) * 2;
    const bool evenT = ((lane & 1) == 0);

    for (int s = 0; s < TT; ++s) {
        const int tcur = dir ? (TT - 1 - s) : s;

        // ---- prefetch Gx for this step (fp32, combined layout)
        float2 gpre[2][2][2];
        #pragma unroll
        for (int mt = 0; mt < 2; ++mt) {
            #pragma unroll
            for (int nt = 0; nt < 2; ++nt) {
                int prow = p0 + mt * 16 + rr;
                int col = gcol + c0 + wid * 16 + nt * 8 + cc2;
                size_t n0i = (size_t)tcur * PP + prow;
                gpre[mt][nt][0] = *(const float2*)&Gx[n0i * G8 + col];
                gpre[mt][nt][1] = *(const float2*)&Gx[(n0i + 8) * G8 + col];
            }
        }

        float acc[2][2][4];
        #pragma unroll
        for (int i = 0; i < 2; ++i)
            #pragma unroll
            for (int j = 0; j < 2; ++j)
                #pragma unroll
                for (int q = 0; q < 4; ++q) acc[i][j][q] = 0.0f;

        if (s > 0) {
            group_barrier(bidx, tid, 8u);

            const int nprev = dir ? (tcur + 1) : (tcur - 1);
            for (int ch = tid; ch < 32 * 32; ch += 256) {
                int row = ch >> 5, cb = ch & 31;
                size_t src = (size_t)(nprev * PP + p0 + row) * D2H + hcol + cb * 8;
                CP_ASYNC16(sb + LP_AHI + row * PRSZ + cb * 16, flatHi + src);
                CP_ASYNC16(sb + LP_ALO + row * PRSZ + cb * 16, flatLo + src);
            }
            CP_COMMIT(); CP_WAIT(0);
            __syncthreads();

            #pragma unroll 4
            for (int kc = 0; kc < 16; ++kc) {
                const uint32_t colOff = (uint32_t)kc * 32 + (uint32_t)(lane >> 4) * 16;
                uint32_t aHi[2][4], bHi[2][2];
                #pragma unroll
                for (int mt = 0; mt < 2; ++mt) {
                    uint32_t ad = (uint32_t)(mt * 16 + (lane & 15)) * PRSZ + colOff;
                    LDSM_X4(aHi[mt], sb + LP_AHI + ad);
                }
                {
                    uint32_t bd = (uint32_t)(wid * 16 + (lane & 15)) * PRSZ + colOff;
                    uint32_t t[4];
                    LDSM_X4(t, sb + LP_BHI + bd);
                    bHi[0][0] = t[0]; bHi[0][1] = t[2];
                    bHi[1][0] = t[1]; bHi[1][1] = t[3];
                }
                #pragma unroll
                for (int mt = 0; mt < 2; ++mt)
                    #pragma unroll
                    for (int nt = 0; nt < 2; ++nt)
                        MMA_FP16(acc[mt][nt], aHi[mt], bHi[nt]);
                {
                    uint32_t aLo[2][4];
                    #pragma unroll
                    for (int mt = 0; mt < 2; ++mt) {
                        uint32_t ad = (uint32_t)(mt * 16 + (lane & 15)) * PRSZ + colOff;
                        LDSM_X4(aLo[mt], sb + LP_ALO + ad);
                    }
                    #pragma unroll
                    for (int mt = 0; mt < 2; ++mt)
                        #pragma unroll
                        for (int nt = 0; nt < 2; ++nt)
                            MMA_FP16(acc[mt][nt], aLo[mt], bHi[nt]);
                }
                {
                    uint32_t bLo[2][2];
                    uint32_t bd = (uint32_t)(wid * 16 + (lane & 15)) * PRSZ + colOff;
                    uint32_t t[4];
                    LDSM_X4(t, sb + LP_BLO + bd);
                    bLo[0][0] = t[0]; bLo[0][1] = t[2];
                    bLo[1][0] = t[1]; bLo[1][1] = t[3];
                    #pragma unroll
                    for (int mt = 0; mt < 2; ++mt)
                        #pragma unroll
                        for (int nt = 0; nt < 2; ++nt)
                            MMA_FP16(acc[mt][nt], aHi[mt], bLo[nt]);
                }
            }
        }

        #pragma unroll
        for (int mt = 0; mt < 2; ++mt) {
            #pragma unroll
            for (int nt = 0; nt < 2; ++nt) {
                int prow = p0 + mt * 16 + rr;
                int col = c0 + wid * 16 + nt * 8 + cc2;
                int j = col >> 2;
                float2 g0 = gpre[mt][nt][0];
                float2 g1 = gpre[mt][nt][1];
                float v0 = acc[mt][nt][0] + g0.x;
                float v1 = acc[mt][nt][1] + g0.y;
                float v2 = acc[mt][nt][2] + g1.x;
                float v3 = acc[mt][nt][3] + g1.y;
                float w0 = __shfl_xor_sync(0xffffffffu, v0, 1);
                float w1 = __shfl_xor_sync(0xffffffffu, v1, 1);
                float w2 = __shfl_xor_sync(0xffffffffu, v2, 1);
                float w3 = __shfl_xor_sync(0xffffffffu, v3, 1);
                float I, F, G, O;
                int p;
                if (evenT) { I = v0; F = v1; G = w0; O = w1; p = prow; }
                else       { I = w2; F = w3; G = v2; O = v3; p = prow + 8; }
                float cold = creg[mt][nt];
                float cn = sigmoidf_(F) * cold + sigmoidf_(I) * tanhf(G);
                float h = sigmoidf_(O) * tanhf(cn);
                creg[mt][nt] = cn;
                size_t nn = (size_t)tcur * PP + p;
                __half hh, hl; splith(h, hh, hl);
                flatHi[nn * D2H + hcol + j] = hh;
                flatLo[nn * D2H + hcol + j] = hl;
            }
        }
        __syncthreads();
    }
}

// ---------------------------------------------------------------------------
// Fused finalize: blocks [0, 3*CC) = pair candidates; [3*CC, 4*CC) = triples.
// ---------------------------------------------------------------------------
__global__ __launch_bounds__(256)
void final_all_kernel(const unsigned* __restrict__ pkeys,
                      const unsigned* __restrict__ tkeys,
                      const float* __restrict__ pair_hb,
                      const float* __restrict__ pair_bo,
                      const float* __restrict__ pair_oW,
                      const float* __restrict__ pair_ob,
                      const float* __restrict__ tri_hb,
                      const float* __restrict__ tri_bo,
                      float* __restrict__ pv, float* __restrict__ tv,
                      float* __restrict__ out) {
    const int b = blockIdx.x;
    if (b < 3 * CC) {
        const int k = b >> 14;
        const unsigned* src = pkeys + (size_t)b * D2H;
        float partial = 0.0f;
        #pragma unroll
        for (int it = 0; it < 2; ++it) {
            int c = threadIdx.x + it * 256;
            unsigned u = src[c];
            float val = u ? (funmap(u) + pair_hb[k * D2H + c]) : pair_bo[k * D2H + c];
            float t = tanhf(val);
            pv[(size_t)b * D2H + c] = t;
            partial += t * pair_oW[k * D2H + c];
        }
        float tot = blockReduceSum256(partial);
        if (threadIdx.x == 0) out[CC + b] = tot + pair_ob[k];
    } else {
        const int s = b - 3 * CC;
        const unsigned* src = tkeys + (size_t)s * D2H;
        #pragma unroll
        for (int it = 0; it < 2; ++it) {
            int c = threadIdx.x + it * 256;
            unsigned u = src[c];
            float val = u ? (funmap(u) + tri_hb[c]) : tri_bo[c];
            tv[(size_t)s * D2H + c] = tanhf(val);
        }
    }
}

// gather 8H features (fp16 hi only)
__global__ void gather_feats_kernel(const float* __restrict__ pv,
                                    const float* __restrict__ tv,
                                    const int* __restrict__ tpi,
                                    __half* __restrict__ fhi) {
    const int s = blockIdx.x;
    const int i0 = tpi[s * 3 + 0];
    const int i1 = tpi[s * 3 + 1];
    const int i2 = tpi[s * 3 + 2];
    for (int j = threadIdx.x; j < 2048; j += blockDim.x) {
        int q = j >> 9, c = j & 511;
        float v;
        if (q == 0)      v = pv[((size_t)2 * CC + i0) * D2H + c];
        else if (q == 1) v = pv[((size_t)1 * CC + i1) * D2H + c];
        else if (q == 2) v = pv[(size_t)i2 * D2H + c];
        else             v = tv[(size_t)s * D2H + c];
        fhi[(size_t)s * 2048 + j] = __float2half(v);
    }
}

__global__ __launch_bounds__(256)
void triple_logit_kernel(const float* __restrict__ fin,
                         const float* __restrict__ tW,
                         const float* __restrict__ tb,
                         float* __restrict__ out) {
    const int s = blockIdx.x;
    float partial = 0.0f;
    #pragma unroll
    for (int it = 0; it < 2; ++it) {
        int c = threadIdx.x + it * 256;
        float v = fin[(size_t)s * D2H + c];
        v = v > 0.0f ? v : 0.0f;
        partial += v * tW[c];
    }
    float tot = blockReduceSum256(partial);
    if (threadIdx.x == 0) out[s] = tot + tb[0];
}

// ---------------------------------------------------------------------------
// Launcher
// ---------------------------------------------------------------------------
extern "C" void kernel_launch(void* const* d_in, const int* in_sizes, int n_in,
                              void* d_out, int out_size) {
    const float* x        = (const float*)d_in[0];
    const float* wih_f    = (const float*)d_in[1];
    const float* whh_f    = (const float*)d_in[2];
    const float* b_f      = (const float*)d_in[3];
    const float* wih_b    = (const float*)d_in[4];
    const float* whh_b    = (const float*)d_in[5];
    const float* b_b      = (const float*)d_in[6];
    const float* pair_hW  = (const float*)d_in[7];
    const float* pair_hb  = (const float*)d_in[8];
    const float* pair_oW  = (const float*)d_in[9];
    const float* pair_ob  = (const float*)d_in[10];
    const float* pair_bo  = (const float*)d_in[11];
    const float* tri_hW   = (const float*)d_in[12];
    const float* tri_hb   = (const float*)d_in[13];
    const float* tri_bo   = (const float*)d_in[14];
    const float* all_hW   = (const float*)d_in[15];
    const float* all_hb   = (const float*)d_in[16];
    const float* out_tW   = (const float*)d_in[17];
    const float* out_tb   = (const float*)d_in[18];
    const int*   occ1     = (const int*)d_in[19];
    const int*   occ2     = (const int*)d_in[20];
    const int*   seg      = (const int*)d_in[21];
    const int*   tri_o1   = (const int*)d_in[22];
    const int*   tri_o2   = (const int*)d_in[23];
    const int*   tri_o3   = (const int*)d_in[24];
    const int*   tri_seg  = (const int*)d_in[25];
    const int*   tri_pi   = (const int*)d_in[26];
    float* out = (float*)d_out;

    float *Gx, *pv, *tv, *fin, *pb;
    unsigned *pk, *tk;
    __half *xHi, *wHi, *flHi, *flLo;
    __half *whF, *wlF, *whB, *wlB;
    __half *pwHi, *twHi, *awHi, *ftHi;
    cudaGetSymbolAddress((void**)&Gx,   g_Gx);
    cudaGetSymbolAddress((void**)&pk,   g_pairKeys);
    cudaGetSymbolAddress((void**)&tk,   g_triKeys);
    cudaGetSymbolAddress((void**)&pv,   g_pv);
    cudaGetSymbolAddress((void**)&tv,   g_tv);
    cudaGetSymbolAddress((void**)&fin,  g_final);
    cudaGetSymbolAddress((void**)&pb,   g_pb);
    cudaGetSymbolAddress((void**)&xHi,  g_xHi);
    cudaGetSymbolAddress((void**)&wHi,  g_wHi);
    cudaGetSymbolAddress((void**)&whF,  g_whhHiF);
    cudaGetSymbolAddress((void**)&wlF,  g_whhLoF);
    cudaGetSymbolAddress((void**)&whB,  g_whhHiB);
    cudaGetSymbolAddress((void**)&wlB,  g_whhLoB);
    cudaGetSymbolAddress((void**)&flHi, g_flatHi);
    cudaGetSymbolAddress((void**)&flLo, g_flatLo);
    cudaGetSymbolAddress((void**)&pwHi, g_pwHi);
    cudaGetSymbolAddress((void**)&twHi, g_twHi);
    cudaGetSymbolAddress((void**)&awHi, g_aWHi);
    cudaGetSymbolAddress((void**)&ftHi, g_ftHi);

    cudaFuncSetAttribute(gemm_fp16x1_kernel,
                         cudaFuncAttributeMaxDynamicSharedMemorySize, SMEM_G1);
    cudaFuncSetAttribute(gemm_gsc_all_kernel,
                         cudaFuncAttributeMaxDynamicSharedMemorySize, SMEM_G1);
    cudaFuncSetAttribute(lstm_persist_kernel,
                         cudaFuncAttributeMaxDynamicSharedMemorySize, SMEM_LSTMP);

    // 1) convert/pack operands (fp16); wih F into rows 0..1023, B into 1024..2047
    convert_pad_kernel<<<4096, 256>>>(x, xHi, NPOS, EE, EP);
    pack_wih_kernel<<<512, 256>>>(wih_f, b_f, wHi, pb);
    pack_wih_kernel<<<512, 256>>>(wih_b, b_b, wHi + (size_t)G4 * EP, pb + G4);
    pack_whh_kernel<<<512, 256>>>(whh_f, whF, wlF);
    pack_whh_kernel<<<512, 256>>>(whh_b, whB, wlB);
    pack_pairWT_kernel<<<3072, 256>>>(pair_hW, pwHi);
    pack_triWT_kernel<<<1536, 256>>>(tri_hW, twHi);
    pack_allWT_kernel<<<1024, 256>>>(all_hW, awHi);

    // 2) fused input projection (both dirs): Gx = xHi @ [wihF|wihB]^T + pb
    gemm_fp16x1_kernel<<<dim3(16, 512), 256, SMEM_G1>>>(xHi, wHi, pb, Gx, EP);

    // 3) zero segment-max keys
    zero_keys_kernel<<<32768, 256>>>(pk, tk);

    // 4) BiLSTM recurrence: persistent HMMA kernel (fp16 3-term)
    lstm_persist_kernel<<<dim3(8, 8, 2), 256, SMEM_LSTMP>>>(
        Gx, whF, wlF, whB, wlB, flHi, flLo);

    // 5) combined gather-GEMM-scatter: all 3 pair types + triples in ONE launch
    gemm_gsc_all_kernel<<<dim3(4, MTILES, 4), 256, SMEM_G1>>>(
        flHi, pwHi, twHi, occ1, occ2, tri_o1, tri_o2, tri_o3,
        seg, tri_seg, pk, tk);

    // 6) fused finalize: pairs (+logits) and triples in one launch
    final_all_kernel<<<4 * CC, 256>>>(pk, tk, pair_hb, pair_bo, pair_oW,
                                      pair_ob, tri_hb, tri_bo, pv, tv, out);

    // 7) final MLP + triple logits (fp16 1-term, contiguous ftHi)
    gather_feats_kernel<<<CC, 256>>>(pv, tv, tri_pi, ftHi);
    gemm_fp16x1_kernel<<<dim3(D2H / 128, CC / 128), 256, SMEM_G1>>>(
        ftHi, awHi, all_hb, fin, 2048);
    triple_logit_kernel<<<CC, 256>>>(fin, out_tW, out_tb, out);
}